// round 10
// baseline (speedup 1.0000x reference)
#include <cuda_runtime.h>
#include <cuda_fp16.h>
#include <cstdint>

// ---------------------------------------------------------------------------
// Swin shifted-window attention, B=32 H=W=56 C=256, 7x7 win, shift 3, 8 heads.
// Plain fp16 GEMMs (K=256), fp32 accumulate, persistent 128x256-tile GEMM.
//
//  1) convert x, qkv_w, proj_w -> fp16
//  2) QKV GEMM (persistent mma.sync, 4-stage cp.async) -> g_qkv fp16 [M,768]
//  3) windowed attention: per-(window,head) tensor-core MMA (49 padded to 64),
//     fused bias+mask+softmax on fragments -> acat fp16 [M,256]
//  4) proj GEMM (same persistent kernel): d_out[M,256] fp32
// ---------------------------------------------------------------------------

#define M_ROWS 100352           // 32*56*56
#define KC     256

__device__ __half g_qkv[100352ULL * 768];
__device__ __half g_x16[100352ULL * 256];
__device__ __half g_acat[100352ULL * 256];
__device__ __half g_wq[768ULL * 256];
__device__ __half g_wp[256ULL * 256];

// ======================= helpers ============================================
__device__ __forceinline__ uint32_t smem_u32(const void* p) {
    uint32_t a;
    asm("{ .reg .u64 t; cvta.to.shared.u64 t, %1; cvt.u32.u64 %0, t; }"
        : "=r"(a) : "l"(p));
    return a;
}
__device__ __forceinline__ uint32_t h2u(__half2 h) {
    union { __half2 h; uint32_t u; } c;
    c.h = h;
    return c.u;
}
__device__ __forceinline__ void cp16(uint32_t s, const void* g) {
    asm volatile("cp.async.cg.shared.global [%0], [%1], 16;"
                 :: "r"(s), "l"(g) : "memory");
}
#define CP_COMMIT() asm volatile("cp.async.commit_group;" ::: "memory")
#define CP_WAIT2()  asm volatile("cp.async.wait_group 2;" ::: "memory")

__device__ __forceinline__ void ldsm4(uint32_t& r0, uint32_t& r1,
                                      uint32_t& r2, uint32_t& r3, uint32_t a) {
    asm volatile("ldmatrix.sync.aligned.m8n8.x4.shared.b16 {%0,%1,%2,%3}, [%4];"
                 : "=r"(r0), "=r"(r1), "=r"(r2), "=r"(r3) : "r"(a));
}
__device__ __forceinline__ void ldsm4t(uint32_t& r0, uint32_t& r1,
                                       uint32_t& r2, uint32_t& r3, uint32_t a) {
    asm volatile(
        "ldmatrix.sync.aligned.m8n8.x4.trans.shared.b16 {%0,%1,%2,%3}, [%4];"
        : "=r"(r0), "=r"(r1), "=r"(r2), "=r"(r3) : "r"(a));
}
__device__ __forceinline__ void mma16816(float* c, const uint32_t* a,
                                         const uint32_t* b) {
    asm volatile(
        "mma.sync.aligned.m16n8k16.row.col.f32.f16.f16.f32 "
        "{%0,%1,%2,%3}, {%4,%5,%6,%7}, {%8,%9}, {%0,%1,%2,%3};"
        : "+f"(c[0]), "+f"(c[1]), "+f"(c[2]), "+f"(c[3])
        : "r"(a[0]), "r"(a[1]), "r"(a[2]), "r"(a[3]), "r"(b[0]), "r"(b[1]));
}

// ======================= fp32 -> fp16 conversion ============================
__global__ void __launch_bounds__(256)
convert_h(const float* __restrict__ in, __half* __restrict__ out, int total4) {
    int t = blockIdx.x * 256 + threadIdx.x;
    if (t >= total4) return;
    float4 v = *(const float4*)(in + (size_t)t * 4);
    *(__half2*)(out + (size_t)t * 4)     = __floats2half2_rn(v.x, v.y);
    *(__half2*)(out + (size_t)t * 4 + 2) = __floats2half2_rn(v.z, v.w);
}

// ======================= persistent mma.sync GEMM ===========================
// C[M,N] = A[M,256] @ W[N,256]^T + bias. CTA tile 128x256, 512 threads,
// 16 warps (4x4), warp tile 32x64, BK=32, 4-stage cp.async pipeline that
// stays warm across tiles (persistent CTAs, flat slab index, lookahead 3).
#define A_ST 10240                    // 128 rows * 80 B
#define B_ST 20480                    // 256 rows * 80 B
#define ST   (A_ST + B_ST)            // 30720 per stage
#define GEMM_SMEM (4 * ST)            // 122880 B

template <typename OT, int NTN>
__global__ void __launch_bounds__(512, 1)
gemm_mma(const __half* __restrict__ A, const __half* __restrict__ W,
         const float* __restrict__ bias, OT* __restrict__ C,
         int N, int ntiles) {
    extern __shared__ __half smbuf[];

    const int tid  = threadIdx.x;
    const int wid  = tid >> 5;
    const int lane = tid & 31;
    const int wm   = wid & 3;          // 4 warps over 128 rows
    const int wn   = wid >> 2;         // 4 warps over 256 cols
    const uint32_t s0 = smem_u32(smbuf);

    // load mapping: A 512 chunks (1/thread), B 1024 chunks (2/thread)
    const int rA = tid >> 2, cA = tid & 3;
    const uint32_t aOff = (rA * 5 + cA) * 16;

    const int mytiles = (ntiles - blockIdx.x + gridDim.x - 1) / gridDim.x;
    const int FT = mytiles * 8;        // flat slab count

#define LOAD_SLAB(f)                                                         \
    do {                                                                     \
        int gt_ = blockIdx.x + ((f) >> 3) * gridDim.x;                       \
        int s_  = (f) & 7;                                                   \
        size_t m0_ = (size_t)(gt_ / NTN) * 128;                              \
        int    n0_ = (gt_ % NTN) * 256;                                      \
        const __half* gA_ = A + (m0_ + rA) * KC + s_ * 32 + cA * 8;          \
        const __half* gB_ = W + (size_t)(n0_ + rA) * KC + s_ * 32 + cA * 8;  \
        uint32_t ab_ = s0 + ((f) & 3) * ST;                                  \
        uint32_t bb_ = ab_ + A_ST;                                           \
        cp16(ab_ + aOff, gA_);                                               \
        cp16(bb_ + aOff, gB_);                                               \
        cp16(bb_ + aOff + A_ST, gB_ + (size_t)128 * KC);                     \
        CP_COMMIT();                                                         \
    } while (0)

    float acc[2][8][4];
#pragma unroll
    for (int i = 0; i < 2; i++)
#pragma unroll
        for (int j = 0; j < 8; j++)
#pragma unroll
            for (int k = 0; k < 4; k++) acc[i][j][k] = 0.f;

    LOAD_SLAB(0);
    LOAD_SLAB(1);
    LOAD_SLAB(2);

    const int aRow = wm * 32 + (lane & 15);
    const int aChk = lane >> 4;
    const int bRowBase = wn * 64 + (lane & 7) + ((lane >> 4) << 3);
    const int bChk = (lane >> 3) & 1;
    const int g  = lane >> 2;
    const int t4 = lane & 3;

    for (int f = 0; f < FT; f++) {
        CP_WAIT2();
        __syncthreads();

        const uint32_t aBase = s0 + (f & 3) * ST;
        const uint32_t bBase = aBase + A_ST;
#pragma unroll
        for (int kk = 0; kk < 2; kk++) {
            uint32_t af[2][4];
#pragma unroll
            for (int mt = 0; mt < 2; mt++) {
                uint32_t ad = aBase +
                    ((aRow + mt * 16) * 5 + kk * 2 + aChk) * 16;
                ldsm4(af[mt][0], af[mt][1], af[mt][2], af[mt][3], ad);
            }
            uint32_t bf[8][2];
#pragma unroll
            for (int pr = 0; pr < 4; pr++) {
                uint32_t bd = bBase +
                    ((bRowBase + pr * 16) * 5 + kk * 2 + bChk) * 16;
                uint32_t r0, r1, r2, r3;
                ldsm4(r0, r1, r2, r3, bd);
                bf[2 * pr][0] = r0; bf[2 * pr][1] = r1;
                bf[2 * pr + 1][0] = r2; bf[2 * pr + 1][1] = r3;
            }
#pragma unroll
            for (int mt = 0; mt < 2; mt++)
#pragma unroll
                for (int nt = 0; nt < 8; nt++)
                    mma16816(acc[mt][nt], af[mt], bf[nt]);
        }

        if ((f & 7) == 7) {
            // ---- epilogue for this tile ----
            int gt = blockIdx.x + (f >> 3) * gridDim.x;
            size_t m0 = (size_t)(gt / NTN) * 128;
            int    n0 = (gt % NTN) * 256;
#pragma unroll
            for (int nt = 0; nt < 8; nt++) {
                const int col = n0 + wn * 64 + nt * 8 + 2 * t4;
                float2 bb = *(const float2*)(bias + col);
#pragma unroll
                for (int mt = 0; mt < 2; mt++) {
                    size_t row0 = m0 + wm * 32 + mt * 16 + g;
                    float v00 = acc[mt][nt][0] + bb.x;
                    float v01 = acc[mt][nt][1] + bb.y;
                    float v10 = acc[mt][nt][2] + bb.x;
                    float v11 = acc[mt][nt][3] + bb.y;
                    if constexpr (sizeof(OT) == 4) {
                        *(float2*)((float*)C + row0 * N + col) =
                            make_float2(v00, v01);
                        *(float2*)((float*)C + (row0 + 8) * N + col) =
                            make_float2(v10, v11);
                    } else {
                        *(__half2*)((__half*)C + row0 * N + col) =
                            __floats2half2_rn(v00, v01);
                        *(__half2*)((__half*)C + (row0 + 8) * N + col) =
                            __floats2half2_rn(v10, v11);
                    }
                }
            }
#pragma unroll
            for (int i = 0; i < 2; i++)
#pragma unroll
                for (int j = 0; j < 8; j++)
#pragma unroll
                    for (int k = 0; k < 4; k++) acc[i][j][k] = 0.f;
        }

        if (f + 3 < FT) LOAD_SLAB(f + 3);
        else CP_COMMIT();
    }
#undef LOAD_SLAB
}

// ======================= tensor-core attention ==============================
// Block = (window, head), 64 threads (2 warps). 49 tokens padded to 64.
__global__ void __launch_bounds__(64)
attn_mma(const __half* __restrict__ qkv, const float* __restrict__ table,
         __half* __restrict__ outp) {
    __shared__ __align__(16) __half Qs[64 * 40];
    __shared__ __align__(16) __half Ks[64 * 40];
    __shared__ __align__(16) __half Vs[64 * 40];
    __shared__ float Bs[169];
    __shared__ int   rowi[49];
    __shared__ int   cinfo[64];

    const int tid  = threadIdx.x;
    const int w    = tid >> 5;
    const int lane = tid & 31;
    const int head = blockIdx.x & 7;
    const int win  = blockIdx.x >> 3;
    const int b    = win >> 6;
    const int wr   = (win >> 3) & 7;
    const int wc   = win & 7;

    if (tid < 49) {
        int ih = tid / 7, iw = tid - ih * 7;
        int oh = wr * 7 + ih + 3; if (oh >= 56) oh -= 56;
        int ow = wc * 7 + iw + 3; if (ow >= 56) ow -= 56;
        rowi[tid] = (b * 56 + oh) * 56 + ow;
    }
    {
        int j = tid;
        int jh = j / 7, jw = j - jh * 7;
        int hj = wr * 7 + jh, wj = wc * 7 + jw;
        int rj = ((hj < 49) ? 0 : (hj < 53 ? 1 : 2)) * 3 +
                 ((wj < 49) ? 0 : (wj < 53 ? 1 : 2));
        cinfo[j] = (jh * 13 + jw) | (rj << 8) | ((j < 49 ? 0 : 1) << 15);
    }
    for (int t = tid; t < 169; t += 64) Bs[t] = table[t * 8 + head];
    for (int idx = tid; idx < 180; idx += 64) {
        int mat = idx / 60, rem = idx - mat * 60;
        int r = 49 + (rem >> 2), q = rem & 3;
        __half* base = (mat == 0) ? Qs : (mat == 1) ? Ks : Vs;
        *(uint4*)(base + r * 40 + q * 8) = make_uint4(0, 0, 0, 0);
    }
    __syncthreads();

    for (int idx = tid; idx < 196; idx += 64) {
        int p = idx >> 2, q = idx & 3;
        const __half* src = qkv + (size_t)rowi[p] * 768 + head * 32 + q * 8;
        *(uint4*)(Qs + p * 40 + q * 8) = *(const uint4*)(src);
        *(uint4*)(Ks + p * 40 + q * 8) = *(const uint4*)(src + 256);
        *(uint4*)(Vs + p * 40 + q * 8) = *(const uint4*)(src + 512);
    }
    __syncthreads();

    const uint32_t sQ = smem_u32(Qs), sK = smem_u32(Ks), sV = smem_u32(Vs);

    uint32_t aQ[2][2][4];
#pragma unroll
    for (int mt = 0; mt < 2; mt++)
#pragma unroll
        for (int kk = 0; kk < 2; kk++) {
            int row = w * 32 + mt * 16 + (lane & 15);
            uint32_t ad = sQ + row * 80 + (kk * 2 + (lane >> 4)) * 16;
            ldsm4(aQ[mt][kk][0], aQ[mt][kk][1], aQ[mt][kk][2], aQ[mt][kk][3], ad);
        }
    uint32_t bK[2][8][2];
#pragma unroll
    for (int kk = 0; kk < 2; kk++)
#pragma unroll
        for (int pr = 0; pr < 4; pr++) {
            int row = pr * 16 + (lane & 7) + ((lane >> 4) << 3);
            uint32_t ad = sK + row * 80 + (kk * 2 + ((lane >> 3) & 1)) * 16;
            uint32_t r0, r1, r2, r3;
            ldsm4(r0, r1, r2, r3, ad);
            bK[kk][2 * pr][0] = r0;     bK[kk][2 * pr][1] = r1;
            bK[kk][2 * pr + 1][0] = r2; bK[kk][2 * pr + 1][1] = r3;
        }
    float s[2][8][4];
#pragma unroll
    for (int mt = 0; mt < 2; mt++)
#pragma unroll
        for (int nt = 0; nt < 8; nt++) {
            s[mt][nt][0] = s[mt][nt][1] = s[mt][nt][2] = s[mt][nt][3] = 0.f;
            mma16816(s[mt][nt], aQ[mt][0], bK[0][nt]);
            mma16816(s[mt][nt], aQ[mt][1], bK[1][nt]);
        }

    const int g  = lane >> 2;
    const int t4 = lane & 3;
    const float scale = 0.17677669529663687f;

    int cp[16];
#pragma unroll
    for (int nt = 0; nt < 8; nt++) {
        cp[2 * nt]     = cinfo[nt * 8 + 2 * t4];
        cp[2 * nt + 1] = cinfo[nt * 8 + 2 * t4 + 1];
    }
    int   rb[2][2], ri[2][2];
    bool  rv[2][2];
#pragma unroll
    for (int mt = 0; mt < 2; mt++)
#pragma unroll
        for (int h = 0; h < 2; h++) {
            int i = w * 32 + mt * 16 + g + 8 * h;
            rv[mt][h] = (i < 49);
            int ih = i / 7, iw = i - ih * 7;
            if (!rv[mt][h]) { ih = 0; iw = 0; }
            rb[mt][h] = (ih + 6) * 13 + iw + 6;
            int hh = wr * 7 + ih, vv = wc * 7 + iw;
            ri[mt][h] = ((hh < 49) ? 0 : (hh < 53 ? 1 : 2)) * 3 +
                        ((vv < 49) ? 0 : (vv < 53 ? 1 : 2));
        }
#pragma unroll
    for (int mt = 0; mt < 2; mt++)
#pragma unroll
        for (int nt = 0; nt < 8; nt++)
#pragma unroll
            for (int e = 0; e < 4; e++) {
                int h = e >> 1, cs = e & 1;
                float v;
                if (!rv[mt][h]) v = 0.f;
                else {
                    int ci = cp[2 * nt + cs];
                    if (ci >> 15) v = -1e4f;
                    else {
                        v = s[mt][nt][e] * scale + Bs[rb[mt][h] - (ci & 0xFF)];
                        if (((ci >> 8) & 0xF) != ri[mt][h]) v -= 100.f;
                    }
                }
                s[mt][nt][e] = v;
            }

    float zinv[2][2];
#pragma unroll
    for (int mt = 0; mt < 2; mt++)
#pragma unroll
        for (int h = 0; h < 2; h++) {
            float m = -1e30f;
#pragma unroll
            for (int nt = 0; nt < 8; nt++) {
                m = fmaxf(m, s[mt][nt][2 * h]);
                m = fmaxf(m, s[mt][nt][2 * h + 1]);
            }
            m = fmaxf(m, __shfl_xor_sync(0xffffffffu, m, 1));
            m = fmaxf(m, __shfl_xor_sync(0xffffffffu, m, 2));
            float sum = 0.f;
#pragma unroll
            for (int nt = 0; nt < 8; nt++) {
                float e0 = __expf(s[mt][nt][2 * h] - m);
                float e1 = __expf(s[mt][nt][2 * h + 1] - m);
                s[mt][nt][2 * h] = e0;
                s[mt][nt][2 * h + 1] = e1;
                sum += e0 + e1;
            }
            sum += __shfl_xor_sync(0xffffffffu, sum, 1);
            sum += __shfl_xor_sync(0xffffffffu, sum, 2);
            zinv[mt][h] = 1.0f / sum;
        }

    uint32_t aP[2][4][4];
#pragma unroll
    for (int mt = 0; mt < 2; mt++)
#pragma unroll
        for (int kt = 0; kt < 4; kt++) {
            aP[mt][kt][0] = h2u(__floats2half2_rn(s[mt][2 * kt][0],
                                                  s[mt][2 * kt][1]));
            aP[mt][kt][1] = h2u(__floats2half2_rn(s[mt][2 * kt][2],
                                                  s[mt][2 * kt][3]));
            aP[mt][kt][2] = h2u(__floats2half2_rn(s[mt][2 * kt + 1][0],
                                                  s[mt][2 * kt + 1][1]));
            aP[mt][kt][3] = h2u(__floats2half2_rn(s[mt][2 * kt + 1][2],
                                                  s[mt][2 * kt + 1][3]));
        }

    uint32_t bV[4][4][2];
#pragma unroll
    for (int kt = 0; kt < 4; kt++)
#pragma unroll
        for (int nh = 0; nh < 2; nh++) {
            int row = kt * 16 + (lane & 7) + (((lane >> 3) & 1) << 3);
            uint32_t ad = sV + row * 80 + nh * 32 + ((lane >> 4) << 4);
            uint32_t r0, r1, r2, r3;
            ldsm4t(r0, r1, r2, r3, ad);
            bV[kt][2 * nh][0] = r0;     bV[kt][2 * nh][1] = r1;
            bV[kt][2 * nh + 1][0] = r2; bV[kt][2 * nh + 1][1] = r3;
        }

    float o[2][4][4];
#pragma unroll
    for (int mt = 0; mt < 2; mt++)
#pragma unroll
        for (int vn = 0; vn < 4; vn++) {
            o[mt][vn][0] = o[mt][vn][1] = o[mt][vn][2] = o[mt][vn][3] = 0.f;
#pragma unroll
            for (int kt = 0; kt < 4; kt++)
                mma16816(o[mt][vn], aP[mt][kt], bV[kt][vn]);
        }

#pragma unroll
    for (int mt = 0; mt < 2; mt++)
#pragma unroll
        for (int h = 0; h < 2; h++) {
            int i = w * 32 + mt * 16 + g + 8 * h;
            if (i >= 49) continue;
            float rz = zinv[mt][h];
            __half* dst = outp + (size_t)rowi[i] * KC + head * 32;
#pragma unroll
            for (int vn = 0; vn < 4; vn++) {
                int col = vn * 8 + 2 * t4;
                *(__half2*)(dst + col) =
                    __floats2half2_rn(o[mt][vn][2 * h] * rz,
                                      o[mt][vn][2 * h + 1] * rz);
            }
        }
}

// ---------------------------------------------------------------------------
extern "C" void kernel_launch(void* const* d_in, const int* in_sizes, int n_in,
                              void* d_out, int out_size) {
    const float* x      = (const float*)d_in[0];
    const float* qkv_w  = (const float*)d_in[1];
    const float* qkv_b  = (const float*)d_in[2];
    const float* proj_w = (const float*)d_in[3];
    const float* proj_b = (const float*)d_in[4];
    const float* table  = (const float*)d_in[5];
    float* out = (float*)d_out;

    void *qkv_p, *x16_p, *acat_p, *wq_p, *wp_p;
    cudaGetSymbolAddress(&qkv_p,  g_qkv);
    cudaGetSymbolAddress(&x16_p,  g_x16);
    cudaGetSymbolAddress(&acat_p, g_acat);
    cudaGetSymbolAddress(&wq_p,   g_wq);
    cudaGetSymbolAddress(&wp_p,   g_wp);
    __half* qkv  = (__half*)qkv_p;
    __half* x16  = (__half*)x16_p;
    __half* acat = (__half*)acat_p;
    __half* wq   = (__half*)wq_p;
    __half* wp   = (__half*)wp_p;

    static int nsm = 0;
    if (!nsm) {
        cudaDeviceGetAttribute(&nsm, cudaDevAttrMultiProcessorCount, 0);
        cudaFuncSetAttribute(gemm_mma<__half, 3>,
                             cudaFuncAttributeMaxDynamicSharedMemorySize,
                             GEMM_SMEM);
        cudaFuncSetAttribute(gemm_mma<float, 1>,
                             cudaFuncAttributeMaxDynamicSharedMemorySize,
                             GEMM_SMEM);
    }

    convert_h<<<(M_ROWS * 64 + 255) / 256, 256>>>(x, x16, M_ROWS * 64);
    convert_h<<<(768 * 64 + 255) / 256, 256>>>(qkv_w, wq, 768 * 64);
    convert_h<<<(256 * 64 + 255) / 256, 256>>>(proj_w, wp, 256 * 64);

    // QKV: M=100352, N=768; tiles = (768/256) x (100352/128) = 3 x 784
    gemm_mma<__half, 3><<<nsm, 512, GEMM_SMEM>>>(x16, wq, qkv_b, qkv,
                                                 768, 3 * 784);

    attn_mma<<<2048 * 8, 64>>>(qkv, table, acat);

    // proj: M=100352, N=256; tiles = 1 x 784
    gemm_mma<float, 1><<<nsm, 512, GEMM_SMEM>>>(acat, wp, proj_b, out,
                                                256, 784);
}

// round 11
// speedup vs baseline: 1.0655x; 1.0655x over previous
#include <cuda_runtime.h>
#include <cuda_fp16.h>
#include <cstdint>

// ---------------------------------------------------------------------------
// Swin shifted-window attention, B=32 H=W=56 C=256, 7x7 win, shift 3, 8 heads.
// Plain fp16 GEMMs (K=256), fp32 accumulate.
//
//  1) convert x, qkv_w, proj_w -> fp16
//  2) QKV GEMM (mma.sync f16, BK=64, 3-stage cp.async) -> g_qkv fp16 [M,768]
//  3) windowed attention: per-(window,head) tensor-core MMA (49 padded to 64),
//     fused bias+mask+softmax on fragments -> acat fp16 [M,256]
//  4) proj GEMM: d_out[M,256] fp32
// ---------------------------------------------------------------------------

#define M_ROWS 100352           // 32*56*56
#define KC     256

__device__ __half g_qkv[100352ULL * 768];
__device__ __half g_x16[100352ULL * 256];
__device__ __half g_acat[100352ULL * 256];
__device__ __half g_wq[768ULL * 256];
__device__ __half g_wp[256ULL * 256];

// ======================= helpers ============================================
__device__ __forceinline__ uint32_t smem_u32(const void* p) {
    uint32_t a;
    asm("{ .reg .u64 t; cvta.to.shared.u64 t, %1; cvt.u32.u64 %0, t; }"
        : "=r"(a) : "l"(p));
    return a;
}
__device__ __forceinline__ uint32_t h2u(__half2 h) {
    union { __half2 h; uint32_t u; } c;
    c.h = h;
    return c.u;
}
__device__ __forceinline__ void cp16(uint32_t s, const void* g) {
    asm volatile("cp.async.cg.shared.global [%0], [%1], 16;"
                 :: "r"(s), "l"(g) : "memory");
}
#define CP_COMMIT() asm volatile("cp.async.commit_group;" ::: "memory")
#define CP_WAIT1()  asm volatile("cp.async.wait_group 1;" ::: "memory")

__device__ __forceinline__ void ldsm4(uint32_t& r0, uint32_t& r1,
                                      uint32_t& r2, uint32_t& r3, uint32_t a) {
    asm volatile("ldmatrix.sync.aligned.m8n8.x4.shared.b16 {%0,%1,%2,%3}, [%4];"
                 : "=r"(r0), "=r"(r1), "=r"(r2), "=r"(r3) : "r"(a));
}
__device__ __forceinline__ void ldsm4t(uint32_t& r0, uint32_t& r1,
                                       uint32_t& r2, uint32_t& r3, uint32_t a) {
    asm volatile(
        "ldmatrix.sync.aligned.m8n8.x4.trans.shared.b16 {%0,%1,%2,%3}, [%4];"
        : "=r"(r0), "=r"(r1), "=r"(r2), "=r"(r3) : "r"(a));
}
__device__ __forceinline__ void mma16816(float* c, const uint32_t* a,
                                         const uint32_t* b) {
    asm volatile(
        "mma.sync.aligned.m16n8k16.row.col.f32.f16.f16.f32 "
        "{%0,%1,%2,%3}, {%4,%5,%6,%7}, {%8,%9}, {%0,%1,%2,%3};"
        : "+f"(c[0]), "+f"(c[1]), "+f"(c[2]), "+f"(c[3])
        : "r"(a[0]), "r"(a[1]), "r"(a[2]), "r"(a[3]), "r"(b[0]), "r"(b[1]));
}

// ======================= fp32 -> fp16 conversion ============================
__global__ void __launch_bounds__(256)
convert_h(const float* __restrict__ in, __half* __restrict__ out, int total4) {
    int t = blockIdx.x * 256 + threadIdx.x;
    if (t >= total4) return;
    float4 v = *(const float4*)(in + (size_t)t * 4);
    *(__half2*)(out + (size_t)t * 4)     = __floats2half2_rn(v.x, v.y);
    *(__half2*)(out + (size_t)t * 4 + 2) = __floats2half2_rn(v.z, v.w);
}

// ======================= mma.sync GEMM (BK=64, 3-stage) =====================
// C[M,N] = A[M,256] @ W[N,256]^T + bias. CTA 128x128, 8 warps (4x2),
// warp tile 32x64, BK=64 slabs (rows padded 128B->144B), 3-stage cp.async,
// ONE barrier per 64-K slab (4 barriers per tile).
#define MROW   144                     // padded row bytes (64 halves + 8 pad)
#define MAT_ST (128 * MROW)            // 18432 B per matrix per stage
#define ST     (2 * MAT_ST)            // 36864 B per stage
#define NSTG   3
#define GEMM_SMEM (NSTG * ST)          // 110592 B

template <typename OT>
__global__ void __launch_bounds__(256, 2)
gemm_mma(const __half* __restrict__ A, const __half* __restrict__ W,
         const float* __restrict__ bias, OT* __restrict__ C, int N) {
    extern __shared__ __half smbuf[];

    const int tid  = threadIdx.x;
    const int wid  = tid >> 5;
    const int lane = tid & 31;
    const int wm   = wid & 3;
    const int wn   = wid >> 2;
    const size_t m0 = (size_t)blockIdx.y * 128;
    const int    n0 = blockIdx.x * 128;
    const uint32_t s0 = smem_u32(smbuf);

    float acc[2][8][4];
#pragma unroll
    for (int i = 0; i < 2; i++)
#pragma unroll
        for (int j = 0; j < 8; j++)
#pragma unroll
            for (int k = 0; k < 4; k++) acc[i][j][k] = 0.f;

    // load mapping: 1024 data chunks per matrix per stage, 4/thread
    // chunk (r, c): r = row 0..127, c = 0..7 (16B units within 128B data)
    const __half* gA = A + m0 * KC;
    const __half* gB = W + (size_t)n0 * KC;

#define LOAD_SLAB(st, slab)                                                  \
    do {                                                                     \
        uint32_t ab_ = s0 + (st) * ST;                                       \
        uint32_t bb_ = ab_ + MAT_ST;                                         \
        int k0_ = (slab) * 64;                                               \
        _Pragma("unroll")                                                    \
        for (int i_ = 0; i_ < 4; i_++) {                                     \
            int seg_ = tid + i_ * 256;                                       \
            int r_ = seg_ >> 3, c_ = seg_ & 7;                               \
            uint32_t so_ = r_ * MROW + c_ * 16;                              \
            cp16(ab_ + so_, gA + (size_t)r_ * KC + k0_ + c_ * 8);            \
            cp16(bb_ + so_, gB + (size_t)r_ * KC + k0_ + c_ * 8);            \
        }                                                                    \
    } while (0)

    const int NS = KC / 64;   // 4 slabs

    LOAD_SLAB(0, 0); CP_COMMIT();
    LOAD_SLAB(1, 1); CP_COMMIT();

    const int aRow = wm * 32 + (lane & 15);
    const int aChk = lane >> 4;
    const int bRowBase = wn * 64 + (lane & 7) + ((lane >> 4) << 3);
    const int bChk = (lane >> 3) & 1;

    for (int f = 0; f < NS; f++) {
        CP_WAIT1();
        __syncthreads();

        const int st = (f < 3) ? f : 0;          // f % 3 for f in [0,4)
        const uint32_t aBase = s0 + st * ST;
        const uint32_t bBase = aBase + MAT_ST;
#pragma unroll
        for (int kk = 0; kk < 4; kk++) {
            uint32_t af[2][4];
#pragma unroll
            for (int mt = 0; mt < 2; mt++) {
                uint32_t ad = aBase + (aRow + mt * 16) * MROW +
                              (kk * 2 + aChk) * 16;
                ldsm4(af[mt][0], af[mt][1], af[mt][2], af[mt][3], ad);
            }
            uint32_t bf[8][2];
#pragma unroll
            for (int pr = 0; pr < 4; pr++) {
                uint32_t bd = bBase + (bRowBase + pr * 16) * MROW +
                              (kk * 2 + bChk) * 16;
                uint32_t r0, r1, r2, r3;
                ldsm4(r0, r1, r2, r3, bd);
                bf[2 * pr][0] = r0; bf[2 * pr][1] = r1;
                bf[2 * pr + 1][0] = r2; bf[2 * pr + 1][1] = r3;
            }
#pragma unroll
            for (int mt = 0; mt < 2; mt++)
#pragma unroll
                for (int nt = 0; nt < 8; nt++)
                    mma16816(acc[mt][nt], af[mt], bf[nt]);
        }

        if (f + 2 < NS) {
            int st2 = f + 2 - 3 < 0 ? f + 2 : f - 1;   // (f+2) % 3
            LOAD_SLAB(st2, f + 2);
        }
        CP_COMMIT();
    }

    const int g  = lane >> 2;
    const int t4 = lane & 3;
#pragma unroll
    for (int nt = 0; nt < 8; nt++) {
        const int col = n0 + wn * 64 + nt * 8 + 2 * t4;
        float2 bb = *(const float2*)(bias + col);
#pragma unroll
        for (int mt = 0; mt < 2; mt++) {
            size_t row0 = m0 + wm * 32 + mt * 16 + g;
            float v00 = acc[mt][nt][0] + bb.x, v01 = acc[mt][nt][1] + bb.y;
            float v10 = acc[mt][nt][2] + bb.x, v11 = acc[mt][nt][3] + bb.y;
            if constexpr (sizeof(OT) == 4) {
                *(float2*)((float*)C + row0 * N + col) = make_float2(v00, v01);
                *(float2*)((float*)C + (row0 + 8) * N + col) = make_float2(v10, v11);
            } else {
                *(__half2*)((__half*)C + row0 * N + col) =
                    __floats2half2_rn(v00, v01);
                *(__half2*)((__half*)C + (row0 + 8) * N + col) =
                    __floats2half2_rn(v10, v11);
            }
        }
    }
#undef LOAD_SLAB
}

// ======================= tensor-core attention ==============================
// Block = (window, head), 64 threads (2 warps). 49 tokens padded to 64.
__global__ void __launch_bounds__(64)
attn_mma(const __half* __restrict__ qkv, const float* __restrict__ table,
         __half* __restrict__ outp) {
    __shared__ __align__(16) __half Qs[64 * 40];
    __shared__ __align__(16) __half Ks[64 * 40];
    __shared__ __align__(16) __half Vs[64 * 40];
    __shared__ float Bs[169];
    __shared__ int   rowi[49];
    __shared__ int   cinfo[64];

    const int tid  = threadIdx.x;
    const int w    = tid >> 5;
    const int lane = tid & 31;
    const int head = blockIdx.x & 7;
    const int win  = blockIdx.x >> 3;
    const int b    = win >> 6;
    const int wr   = (win >> 3) & 7;
    const int wc   = win & 7;

    if (tid < 49) {
        int ih = tid / 7, iw = tid - ih * 7;
        int oh = wr * 7 + ih + 3; if (oh >= 56) oh -= 56;
        int ow = wc * 7 + iw + 3; if (ow >= 56) ow -= 56;
        rowi[tid] = (b * 56 + oh) * 56 + ow;
    }
    {
        int j = tid;
        int jh = j / 7, jw = j - jh * 7;
        int hj = wr * 7 + jh, wj = wc * 7 + jw;
        int rj = ((hj < 49) ? 0 : (hj < 53 ? 1 : 2)) * 3 +
                 ((wj < 49) ? 0 : (wj < 53 ? 1 : 2));
        cinfo[j] = (jh * 13 + jw) | (rj << 8) | ((j < 49 ? 0 : 1) << 15);
    }
    for (int t = tid; t < 169; t += 64) Bs[t] = table[t * 8 + head];
    for (int idx = tid; idx < 180; idx += 64) {
        int mat = idx / 60, rem = idx - mat * 60;
        int r = 49 + (rem >> 2), q = rem & 3;
        __half* base = (mat == 0) ? Qs : (mat == 1) ? Ks : Vs;
        *(uint4*)(base + r * 40 + q * 8) = make_uint4(0, 0, 0, 0);
    }
    __syncthreads();

    for (int idx = tid; idx < 196; idx += 64) {
        int p = idx >> 2, q = idx & 3;
        const __half* src = qkv + (size_t)rowi[p] * 768 + head * 32 + q * 8;
        *(uint4*)(Qs + p * 40 + q * 8) = *(const uint4*)(src);
        *(uint4*)(Ks + p * 40 + q * 8) = *(const uint4*)(src + 256);
        *(uint4*)(Vs + p * 40 + q * 8) = *(const uint4*)(src + 512);
    }
    __syncthreads();

    const uint32_t sQ = smem_u32(Qs), sK = smem_u32(Ks), sV = smem_u32(Vs);

    uint32_t aQ[2][2][4];
#pragma unroll
    for (int mt = 0; mt < 2; mt++)
#pragma unroll
        for (int kk = 0; kk < 2; kk++) {
            int row = w * 32 + mt * 16 + (lane & 15);
            uint32_t ad = sQ + row * 80 + (kk * 2 + (lane >> 4)) * 16;
            ldsm4(aQ[mt][kk][0], aQ[mt][kk][1], aQ[mt][kk][2], aQ[mt][kk][3], ad);
        }
    uint32_t bK[2][8][2];
#pragma unroll
    for (int kk = 0; kk < 2; kk++)
#pragma unroll
        for (int pr = 0; pr < 4; pr++) {
            int row = pr * 16 + (lane & 7) + ((lane >> 4) << 3);
            uint32_t ad = sK + row * 80 + (kk * 2 + ((lane >> 3) & 1)) * 16;
            uint32_t r0, r1, r2, r3;
            ldsm4(r0, r1, r2, r3, ad);
            bK[kk][2 * pr][0] = r0;     bK[kk][2 * pr][1] = r1;
            bK[kk][2 * pr + 1][0] = r2; bK[kk][2 * pr + 1][1] = r3;
        }
    float s[2][8][4];
#pragma unroll
    for (int mt = 0; mt < 2; mt++)
#pragma unroll
        for (int nt = 0; nt < 8; nt++) {
            s[mt][nt][0] = s[mt][nt][1] = s[mt][nt][2] = s[mt][nt][3] = 0.f;
            mma16816(s[mt][nt], aQ[mt][0], bK[0][nt]);
            mma16816(s[mt][nt], aQ[mt][1], bK[1][nt]);
        }

    const int g  = lane >> 2;
    const int t4 = lane & 3;
    const float scale = 0.17677669529663687f;

    int cp[16];
#pragma unroll
    for (int nt = 0; nt < 8; nt++) {
        cp[2 * nt]     = cinfo[nt * 8 + 2 * t4];
        cp[2 * nt + 1] = cinfo[nt * 8 + 2 * t4 + 1];
    }
    int   rb[2][2], ri[2][2];
    bool  rv[2][2];
#pragma unroll
    for (int mt = 0; mt < 2; mt++)
#pragma unroll
        for (int h = 0; h < 2; h++) {
            int i = w * 32 + mt * 16 + g + 8 * h;
            rv[mt][h] = (i < 49);
            int ih = i / 7, iw = i - ih * 7;
            if (!rv[mt][h]) { ih = 0; iw = 0; }
            rb[mt][h] = (ih + 6) * 13 + iw + 6;
            int hh = wr * 7 + ih, vv = wc * 7 + iw;
            ri[mt][h] = ((hh < 49) ? 0 : (hh < 53 ? 1 : 2)) * 3 +
                        ((vv < 49) ? 0 : (vv < 53 ? 1 : 2));
        }
#pragma unroll
    for (int mt = 0; mt < 2; mt++)
#pragma unroll
        for (int nt = 0; nt < 8; nt++)
#pragma unroll
            for (int e = 0; e < 4; e++) {
                int h = e >> 1, cs = e & 1;
                float v;
                if (!rv[mt][h]) v = 0.f;
                else {
                    int ci = cp[2 * nt + cs];
                    if (ci >> 15) v = -1e4f;
                    else {
                        v = s[mt][nt][e] * scale + Bs[rb[mt][h] - (ci & 0xFF)];
                        if (((ci >> 8) & 0xF) != ri[mt][h]) v -= 100.f;
                    }
                }
                s[mt][nt][e] = v;
            }

    float zinv[2][2];
#pragma unroll
    for (int mt = 0; mt < 2; mt++)
#pragma unroll
        for (int h = 0; h < 2; h++) {
            float m = -1e30f;
#pragma unroll
            for (int nt = 0; nt < 8; nt++) {
                m = fmaxf(m, s[mt][nt][2 * h]);
                m = fmaxf(m, s[mt][nt][2 * h + 1]);
            }
            m = fmaxf(m, __shfl_xor_sync(0xffffffffu, m, 1));
            m = fmaxf(m, __shfl_xor_sync(0xffffffffu, m, 2));
            float sum = 0.f;
#pragma unroll
            for (int nt = 0; nt < 8; nt++) {
                float e0 = __expf(s[mt][nt][2 * h] - m);
                float e1 = __expf(s[mt][nt][2 * h + 1] - m);
                s[mt][nt][2 * h] = e0;
                s[mt][nt][2 * h + 1] = e1;
                sum += e0 + e1;
            }
            sum += __shfl_xor_sync(0xffffffffu, sum, 1);
            sum += __shfl_xor_sync(0xffffffffu, sum, 2);
            zinv[mt][h] = 1.0f / sum;
        }

    uint32_t aP[2][4][4];
#pragma unroll
    for (int mt = 0; mt < 2; mt++)
#pragma unroll
        for (int kt = 0; kt < 4; kt++) {
            aP[mt][kt][0] = h2u(__floats2half2_rn(s[mt][2 * kt][0],
                                                  s[mt][2 * kt][1]));
            aP[mt][kt][1] = h2u(__floats2half2_rn(s[mt][2 * kt][2],
                                                  s[mt][2 * kt][3]));
            aP[mt][kt][2] = h2u(__floats2half2_rn(s[mt][2 * kt + 1][0],
                                                  s[mt][2 * kt + 1][1]));
            aP[mt][kt][3] = h2u(__floats2half2_rn(s[mt][2 * kt + 1][2],
                                                  s[mt][2 * kt + 1][3]));
        }

    uint32_t bV[4][4][2];
#pragma unroll
    for (int kt = 0; kt < 4; kt++)
#pragma unroll
        for (int nh = 0; nh < 2; nh++) {
            int row = kt * 16 + (lane & 7) + (((lane >> 3) & 1) << 3);
            uint32_t ad = sV + row * 80 + nh * 32 + ((lane >> 4) << 4);
            uint32_t r0, r1, r2, r3;
            ldsm4t(r0, r1, r2, r3, ad);
            bV[kt][2 * nh][0] = r0;     bV[kt][2 * nh][1] = r1;
            bV[kt][2 * nh + 1][0] = r2; bV[kt][2 * nh + 1][1] = r3;
        }

    float o[2][4][4];
#pragma unroll
    for (int mt = 0; mt < 2; mt++)
#pragma unroll
        for (int vn = 0; vn < 4; vn++) {
            o[mt][vn][0] = o[mt][vn][1] = o[mt][vn][2] = o[mt][vn][3] = 0.f;
#pragma unroll
            for (int kt = 0; kt < 4; kt++)
                mma16816(o[mt][vn], aP[mt][kt], bV[kt][vn]);
        }

#pragma unroll
    for (int mt = 0; mt < 2; mt++)
#pragma unroll
        for (int h = 0; h < 2; h++) {
            int i = w * 32 + mt * 16 + g + 8 * h;
            if (i >= 49) continue;
            float rz = zinv[mt][h];
            __half* dst = outp + (size_t)rowi[i] * KC + head * 32;
#pragma unroll
            for (int vn = 0; vn < 4; vn++) {
                int col = vn * 8 + 2 * t4;
                *(__half2*)(dst + col) =
                    __floats2half2_rn(o[mt][vn][2 * h] * rz,
                                      o[mt][vn][2 * h + 1] * rz);
            }
        }
}

// ---------------------------------------------------------------------------
extern "C" void kernel_launch(void* const* d_in, const int* in_sizes, int n_in,
                              void* d_out, int out_size) {
    const float* x      = (const float*)d_in[0];
    const float* qkv_w  = (const float*)d_in[1];
    const float* qkv_b  = (const float*)d_in[2];
    const float* proj_w = (const float*)d_in[3];
    const float* proj_b = (const float*)d_in[4];
    const float* table  = (const float*)d_in[5];
    float* out = (float*)d_out;

    void *qkv_p, *x16_p, *acat_p, *wq_p, *wp_p;
    cudaGetSymbolAddress(&qkv_p,  g_qkv);
    cudaGetSymbolAddress(&x16_p,  g_x16);
    cudaGetSymbolAddress(&acat_p, g_acat);
    cudaGetSymbolAddress(&wq_p,   g_wq);
    cudaGetSymbolAddress(&wp_p,   g_wp);
    __half* qkv  = (__half*)qkv_p;
    __half* x16  = (__half*)x16_p;
    __half* acat = (__half*)acat_p;
    __half* wq   = (__half*)wq_p;
    __half* wp   = (__half*)wp_p;

    static bool attr_done = false;
    if (!attr_done) {
        cudaFuncSetAttribute(gemm_mma<__half>,
                             cudaFuncAttributeMaxDynamicSharedMemorySize,
                             GEMM_SMEM);
        cudaFuncSetAttribute(gemm_mma<float>,
                             cudaFuncAttributeMaxDynamicSharedMemorySize,
                             GEMM_SMEM);
        attr_done = true;
    }

    convert_h<<<(M_ROWS * 64 + 255) / 256, 256>>>(x, x16, M_ROWS * 64);
    convert_h<<<(768 * 64 + 255) / 256, 256>>>(qkv_w, wq, 768 * 64);
    convert_h<<<(256 * 64 + 255) / 256, 256>>>(proj_w, wp, 256 * 64);

    dim3 gq(768 / 128, M_ROWS / 128);
    gemm_mma<__half><<<gq, 256, GEMM_SMEM>>>(x16, wq, qkv_b, qkv, 768);

    attn_mma<<<2048 * 8, 64>>>(qkv, table, acat);

    dim3 gp(256 / 128, M_ROWS / 128);
    gemm_mma<float><<<gp, 256, GEMM_SMEM>>>(acat, wp, proj_b, out, 256);
}

// round 12
// speedup vs baseline: 1.1086x; 1.0404x over previous
#include <cuda_runtime.h>
#include <cuda_fp16.h>
#include <cstdint>

// ---------------------------------------------------------------------------
// Swin shifted-window attention, B=32 H=W=56 C=256, 7x7 win, shift 3, 8 heads.
// Plain fp16 GEMMs (K=256), fp32 accumulate.
//
//  1) convert x, qkv_w, proj_w -> fp16; build bias+mask table [4][8][64][64]
//  2) QKV GEMM (mma.sync f16, BK=64, 3-stage cp.async) -> g_qkv fp16 [M,768]
//  3) windowed attention: per-(window,head) tensor-core MMA, fused
//     table-lookup logits + softmax on fragments -> acat fp16 [M,256]
//  4) proj GEMM: d_out[M,256] fp32
// ---------------------------------------------------------------------------

#define M_ROWS 100352           // 32*56*56
#define KC     256

__device__ __half g_qkv[100352ULL * 768];
__device__ __half g_x16[100352ULL * 256];
__device__ __half g_acat[100352ULL * 256];
__device__ __half g_wq[768ULL * 256];
__device__ __half g_wp[256ULL * 256];
__device__ __half g_tbl[4 * 8 * 64 * 64];   // bias+mask per (type, head)

// ======================= helpers ============================================
__device__ __forceinline__ uint32_t smem_u32(const void* p) {
    uint32_t a;
    asm("{ .reg .u64 t; cvta.to.shared.u64 t, %1; cvt.u32.u64 %0, t; }"
        : "=r"(a) : "l"(p));
    return a;
}
__device__ __forceinline__ uint32_t h2u(__half2 h) {
    union { __half2 h; uint32_t u; } c;
    c.h = h;
    return c.u;
}
__device__ __forceinline__ void cp16(uint32_t s, const void* g) {
    asm volatile("cp.async.cg.shared.global [%0], [%1], 16;"
                 :: "r"(s), "l"(g) : "memory");
}
#define CP_COMMIT() asm volatile("cp.async.commit_group;" ::: "memory")
#define CP_WAIT1()  asm volatile("cp.async.wait_group 1;" ::: "memory")

__device__ __forceinline__ void ldsm4(uint32_t& r0, uint32_t& r1,
                                      uint32_t& r2, uint32_t& r3, uint32_t a) {
    asm volatile("ldmatrix.sync.aligned.m8n8.x4.shared.b16 {%0,%1,%2,%3}, [%4];"
                 : "=r"(r0), "=r"(r1), "=r"(r2), "=r"(r3) : "r"(a));
}
__device__ __forceinline__ void ldsm4t(uint32_t& r0, uint32_t& r1,
                                       uint32_t& r2, uint32_t& r3, uint32_t a) {
    asm volatile(
        "ldmatrix.sync.aligned.m8n8.x4.trans.shared.b16 {%0,%1,%2,%3}, [%4];"
        : "=r"(r0), "=r"(r1), "=r"(r2), "=r"(r3) : "r"(a));
}
__device__ __forceinline__ void mma16816(float* c, const uint32_t* a,
                                         const uint32_t* b) {
    asm volatile(
        "mma.sync.aligned.m16n8k16.row.col.f32.f16.f16.f32 "
        "{%0,%1,%2,%3}, {%4,%5,%6,%7}, {%8,%9}, {%0,%1,%2,%3};"
        : "+f"(c[0]), "+f"(c[1]), "+f"(c[2]), "+f"(c[3])
        : "r"(a[0]), "r"(a[1]), "r"(a[2]), "r"(a[3]), "r"(b[0]), "r"(b[1]));
}

// ======================= fp32 -> fp16 conversion ============================
__global__ void __launch_bounds__(256)
convert_h(const float* __restrict__ in, __half* __restrict__ out, int total4) {
    int t = blockIdx.x * 256 + threadIdx.x;
    if (t >= total4) return;
    float4 v = *(const float4*)(in + (size_t)t * 4);
    *(__half2*)(out + (size_t)t * 4)     = __floats2half2_rn(v.x, v.y);
    *(__half2*)(out + (size_t)t * 4 + 2) = __floats2half2_rn(v.z, v.w);
}

// ======================= bias+mask table build ==============================
// tbl[type][head][i][j] = rel_bias(head,i,j) + shift_mask(type,i,j)
// type = (wr==7)*2 + (wc==7); pad cols j>=49 -> -1e4, pad rows i>=49 -> 0.
__global__ void __launch_bounds__(256)
build_tbl(const float* __restrict__ table, __half* __restrict__ tbl) {
    int type = blockIdx.x >> 3;
    int head = blockIdx.x & 7;
    int wr = (type & 2) ? 7 : 0;
    int wc = (type & 1) ? 7 : 0;
    for (int idx = threadIdx.x; idx < 4096; idx += 256) {
        int i = idx >> 6, j = idx & 63;
        float v;
        if (j >= 49)      v = -1e4f;
        else if (i >= 49) v = 0.f;
        else {
            int ih = i / 7, iw = i - ih * 7;
            int jh = j / 7, jw = j - jh * 7;
            float bias = table[((ih - jh + 6) * 13 + (iw - jw + 6)) * 8 + head];
            int hh = wr * 7 + ih, vv = wc * 7 + iw;
            int hj = wr * 7 + jh, wj = wc * 7 + jw;
            int ri = ((hh < 49) ? 0 : (hh < 53 ? 1 : 2)) * 3 +
                     ((vv < 49) ? 0 : (vv < 53 ? 1 : 2));
            int rj = ((hj < 49) ? 0 : (hj < 53 ? 1 : 2)) * 3 +
                     ((wj < 49) ? 0 : (wj < 53 ? 1 : 2));
            v = bias + ((ri != rj) ? -100.f : 0.f);
        }
        tbl[(size_t)blockIdx.x * 4096 + idx] = __float2half_rn(v);
    }
}

// ======================= mma.sync GEMM (BK=64, 3-stage) =====================
#define MROW   144
#define MAT_ST (128 * MROW)
#define ST     (2 * MAT_ST)
#define NSTG   3
#define GEMM_SMEM (NSTG * ST)         // 110592 B

template <typename OT>
__global__ void __launch_bounds__(256, 2)
gemm_mma(const __half* __restrict__ A, const __half* __restrict__ W,
         const float* __restrict__ bias, OT* __restrict__ C, int N) {
    extern __shared__ __half smbuf[];

    const int tid  = threadIdx.x;
    const int wid  = tid >> 5;
    const int lane = tid & 31;
    const int wm   = wid & 3;
    const int wn   = wid >> 2;
    const size_t m0 = (size_t)blockIdx.y * 128;
    const int    n0 = blockIdx.x * 128;
    const uint32_t s0 = smem_u32(smbuf);

    float acc[2][8][4];
#pragma unroll
    for (int i = 0; i < 2; i++)
#pragma unroll
        for (int j = 0; j < 8; j++)
#pragma unroll
            for (int k = 0; k < 4; k++) acc[i][j][k] = 0.f;

    const __half* gA = A + m0 * KC;
    const __half* gB = W + (size_t)n0 * KC;

#define LOAD_SLAB(st, slab)                                                  \
    do {                                                                     \
        uint32_t ab_ = s0 + (st) * ST;                                       \
        uint32_t bb_ = ab_ + MAT_ST;                                         \
        int k0_ = (slab) * 64;                                               \
        _Pragma("unroll")                                                    \
        for (int i_ = 0; i_ < 4; i_++) {                                     \
            int seg_ = tid + i_ * 256;                                       \
            int r_ = seg_ >> 3, c_ = seg_ & 7;                               \
            uint32_t so_ = r_ * MROW + c_ * 16;                              \
            cp16(ab_ + so_, gA + (size_t)r_ * KC + k0_ + c_ * 8);            \
            cp16(bb_ + so_, gB + (size_t)r_ * KC + k0_ + c_ * 8);            \
        }                                                                    \
    } while (0)

    const int NS = KC / 64;

    LOAD_SLAB(0, 0); CP_COMMIT();
    LOAD_SLAB(1, 1); CP_COMMIT();

    const int aRow = wm * 32 + (lane & 15);
    const int aChk = lane >> 4;
    const int bRowBase = wn * 64 + (lane & 7) + ((lane >> 4) << 3);
    const int bChk = (lane >> 3) & 1;

    for (int f = 0; f < NS; f++) {
        CP_WAIT1();
        __syncthreads();

        const int st = (f < 3) ? f : 0;
        const uint32_t aBase = s0 + st * ST;
        const uint32_t bBase = aBase + MAT_ST;
#pragma unroll
        for (int kk = 0; kk < 4; kk++) {
            uint32_t af[2][4];
#pragma unroll
            for (int mt = 0; mt < 2; mt++) {
                uint32_t ad = aBase + (aRow + mt * 16) * MROW +
                              (kk * 2 + aChk) * 16;
                ldsm4(af[mt][0], af[mt][1], af[mt][2], af[mt][3], ad);
            }
            uint32_t bf[8][2];
#pragma unroll
            for (int pr = 0; pr < 4; pr++) {
                uint32_t bd = bBase + (bRowBase + pr * 16) * MROW +
                              (kk * 2 + bChk) * 16;
                uint32_t r0, r1, r2, r3;
                ldsm4(r0, r1, r2, r3, bd);
                bf[2 * pr][0] = r0; bf[2 * pr][1] = r1;
                bf[2 * pr + 1][0] = r2; bf[2 * pr + 1][1] = r3;
            }
#pragma unroll
            for (int mt = 0; mt < 2; mt++)
#pragma unroll
                for (int nt = 0; nt < 8; nt++)
                    mma16816(acc[mt][nt], af[mt], bf[nt]);
        }

        if (f + 2 < NS) {
            int st2 = f + 2 - 3 < 0 ? f + 2 : f - 1;
            LOAD_SLAB(st2, f + 2);
        }
        CP_COMMIT();
    }

    const int g  = lane >> 2;
    const int t4 = lane & 3;
#pragma unroll
    for (int nt = 0; nt < 8; nt++) {
        const int col = n0 + wn * 64 + nt * 8 + 2 * t4;
        float2 bb = *(const float2*)(bias + col);
#pragma unroll
        for (int mt = 0; mt < 2; mt++) {
            size_t row0 = m0 + wm * 32 + mt * 16 + g;
            float v00 = acc[mt][nt][0] + bb.x, v01 = acc[mt][nt][1] + bb.y;
            float v10 = acc[mt][nt][2] + bb.x, v11 = acc[mt][nt][3] + bb.y;
            if constexpr (sizeof(OT) == 4) {
                *(float2*)((float*)C + row0 * N + col) = make_float2(v00, v01);
                *(float2*)((float*)C + (row0 + 8) * N + col) = make_float2(v10, v11);
            } else {
                *(__half2*)((__half*)C + row0 * N + col) =
                    __floats2half2_rn(v00, v01);
                *(__half2*)((__half*)C + (row0 + 8) * N + col) =
                    __floats2half2_rn(v10, v11);
            }
        }
    }
#undef LOAD_SLAB
}

// ======================= tensor-core attention ==============================
// Block = (window, head), 64 threads (2 warps). 49 tokens padded to 64.
// Logits = S*scale + Ts[i][j] (precomputed bias+mask, fp16, stride 72).
__global__ void __launch_bounds__(64)
attn_mma(const __half* __restrict__ qkv, const __half* __restrict__ tblg,
         __half* __restrict__ outp) {
    __shared__ __align__(16) __half Qs[64 * 40];
    __shared__ __align__(16) __half Ks[64 * 40];
    __shared__ __align__(16) __half Vs[64 * 40];
    __shared__ __align__(16) __half Ts[64 * 72];
    __shared__ int rowi[49];

    const int tid  = threadIdx.x;
    const int w    = tid >> 5;
    const int lane = tid & 31;
    const int head = blockIdx.x & 7;
    const int win  = blockIdx.x >> 3;
    const int b    = win >> 6;
    const int wr   = (win >> 3) & 7;
    const int wc   = win & 7;

    if (tid < 49) {
        int ih = tid / 7, iw = tid - ih * 7;
        int oh = wr * 7 + ih + 3; if (oh >= 56) oh -= 56;
        int ow = wc * 7 + iw + 3; if (ow >= 56) ow -= 56;
        rowi[tid] = (b * 56 + oh) * 56 + ow;
    }
    // stage bias+mask table (4096 halves = 512 uint4)
    {
        const int type = ((wr == 7) ? 2 : 0) | ((wc == 7) ? 1 : 0);
        const uint4* Tg = (const uint4*)(tblg + (size_t)(type * 8 + head) * 4096);
        for (int idx = tid; idx < 512; idx += 64) {
            int r = idx >> 3, c = idx & 7;
            *(uint4*)(Ts + r * 72 + c * 8) = Tg[idx];
        }
    }
    // zero pad rows 49..63 of Q,K,V
    for (int idx = tid; idx < 180; idx += 64) {
        int mat = idx / 60, rem = idx - mat * 60;
        int r = 49 + (rem >> 2), q = rem & 3;
        __half* base = (mat == 0) ? Qs : (mat == 1) ? Ks : Vs;
        *(uint4*)(base + r * 40 + q * 8) = make_uint4(0, 0, 0, 0);
    }
    __syncthreads();

    for (int idx = tid; idx < 196; idx += 64) {
        int p = idx >> 2, q = idx & 3;
        const __half* src = qkv + (size_t)rowi[p] * 768 + head * 32 + q * 8;
        *(uint4*)(Qs + p * 40 + q * 8) = *(const uint4*)(src);
        *(uint4*)(Ks + p * 40 + q * 8) = *(const uint4*)(src + 256);
        *(uint4*)(Vs + p * 40 + q * 8) = *(const uint4*)(src + 512);
    }
    __syncthreads();

    const uint32_t sQ = smem_u32(Qs), sK = smem_u32(Ks), sV = smem_u32(Vs);

    // ---- S = Q K^T ----
    uint32_t aQ[2][2][4];
#pragma unroll
    for (int mt = 0; mt < 2; mt++)
#pragma unroll
        for (int kk = 0; kk < 2; kk++) {
            int row = w * 32 + mt * 16 + (lane & 15);
            uint32_t ad = sQ + row * 80 + (kk * 2 + (lane >> 4)) * 16;
            ldsm4(aQ[mt][kk][0], aQ[mt][kk][1], aQ[mt][kk][2], aQ[mt][kk][3], ad);
        }
    uint32_t bK[2][8][2];
#pragma unroll
    for (int kk = 0; kk < 2; kk++)
#pragma unroll
        for (int pr = 0; pr < 4; pr++) {
            int row = pr * 16 + (lane & 7) + ((lane >> 4) << 3);
            uint32_t ad = sK + row * 80 + (kk * 2 + ((lane >> 3) & 1)) * 16;
            uint32_t r0, r1, r2, r3;
            ldsm4(r0, r1, r2, r3, ad);
            bK[kk][2 * pr][0] = r0;     bK[kk][2 * pr][1] = r1;
            bK[kk][2 * pr + 1][0] = r2; bK[kk][2 * pr + 1][1] = r3;
        }
    float s[2][8][4];
#pragma unroll
    for (int mt = 0; mt < 2; mt++)
#pragma unroll
        for (int nt = 0; nt < 8; nt++) {
            s[mt][nt][0] = s[mt][nt][1] = s[mt][nt][2] = s[mt][nt][3] = 0.f;
            mma16816(s[mt][nt], aQ[mt][0], bK[0][nt]);
            mma16816(s[mt][nt], aQ[mt][1], bK[1][nt]);
        }

    const int g  = lane >> 2;
    const int t4 = lane & 3;
    const float scale = 0.17677669529663687f;

    // ---- logits: s*scale + table ----
#pragma unroll
    for (int mt = 0; mt < 2; mt++)
#pragma unroll
        for (int h = 0; h < 2; h++) {
            const __half* trow = Ts + (w * 32 + mt * 16 + g + 8 * h) * 72;
#pragma unroll
            for (int nt = 0; nt < 8; nt++) {
                __half2 t2 = *(const __half2*)(trow + nt * 8 + 2 * t4);
                float2 tf = __half22float2(t2);
                s[mt][nt][2 * h]     = fmaf(s[mt][nt][2 * h],     scale, tf.x);
                s[mt][nt][2 * h + 1] = fmaf(s[mt][nt][2 * h + 1], scale, tf.y);
            }
        }

    // ---- softmax ----
    float zinv[2][2];
#pragma unroll
    for (int mt = 0; mt < 2; mt++)
#pragma unroll
        for (int h = 0; h < 2; h++) {
            float m = -1e30f;
#pragma unroll
            for (int nt = 0; nt < 8; nt++) {
                m = fmaxf(m, s[mt][nt][2 * h]);
                m = fmaxf(m, s[mt][nt][2 * h + 1]);
            }
            m = fmaxf(m, __shfl_xor_sync(0xffffffffu, m, 1));
            m = fmaxf(m, __shfl_xor_sync(0xffffffffu, m, 2));
            float sum = 0.f;
#pragma unroll
            for (int nt = 0; nt < 8; nt++) {
                float e0 = __expf(s[mt][nt][2 * h] - m);
                float e1 = __expf(s[mt][nt][2 * h + 1] - m);
                s[mt][nt][2 * h] = e0;
                s[mt][nt][2 * h + 1] = e1;
                sum += e0 + e1;
            }
            sum += __shfl_xor_sync(0xffffffffu, sum, 1);
            sum += __shfl_xor_sync(0xffffffffu, sum, 2);
            zinv[mt][h] = 1.0f / sum;
        }

    uint32_t aP[2][4][4];
#pragma unroll
    for (int mt = 0; mt < 2; mt++)
#pragma unroll
        for (int kt = 0; kt < 4; kt++) {
            aP[mt][kt][0] = h2u(__floats2half2_rn(s[mt][2 * kt][0],
                                                  s[mt][2 * kt][1]));
            aP[mt][kt][1] = h2u(__floats2half2_rn(s[mt][2 * kt][2],
                                                  s[mt][2 * kt][3]));
            aP[mt][kt][2] = h2u(__floats2half2_rn(s[mt][2 * kt + 1][0],
                                                  s[mt][2 * kt + 1][1]));
            aP[mt][kt][3] = h2u(__floats2half2_rn(s[mt][2 * kt + 1][2],
                                                  s[mt][2 * kt + 1][3]));
        }

    uint32_t bV[4][4][2];
#pragma unroll
    for (int kt = 0; kt < 4; kt++)
#pragma unroll
        for (int nh = 0; nh < 2; nh++) {
            int row = kt * 16 + (lane & 7) + (((lane >> 3) & 1) << 3);
            uint32_t ad = sV + row * 80 + nh * 32 + ((lane >> 4) << 4);
            uint32_t r0, r1, r2, r3;
            ldsm4t(r0, r1, r2, r3, ad);
            bV[kt][2 * nh][0] = r0;     bV[kt][2 * nh][1] = r1;
            bV[kt][2 * nh + 1][0] = r2; bV[kt][2 * nh + 1][1] = r3;
        }

    float o[2][4][4];
#pragma unroll
    for (int mt = 0; mt < 2; mt++)
#pragma unroll
        for (int vn = 0; vn < 4; vn++) {
            o[mt][vn][0] = o[mt][vn][1] = o[mt][vn][2] = o[mt][vn][3] = 0.f;
#pragma unroll
            for (int kt = 0; kt < 4; kt++)
                mma16816(o[mt][vn], aP[mt][kt], bV[kt][vn]);
        }

#pragma unroll
    for (int mt = 0; mt < 2; mt++)
#pragma unroll
        for (int h = 0; h < 2; h++) {
            int i = w * 32 + mt * 16 + g + 8 * h;
            if (i >= 49) continue;
            float rz = zinv[mt][h];
            __half* dst = outp + (size_t)rowi[i] * KC + head * 32;
#pragma unroll
            for (int vn = 0; vn < 4; vn++) {
                int col = vn * 8 + 2 * t4;
                *(__half2*)(dst + col) =
                    __floats2half2_rn(o[mt][vn][2 * h] * rz,
                                      o[mt][vn][2 * h + 1] * rz);
            }
        }
}

// ---------------------------------------------------------------------------
extern "C" void kernel_launch(void* const* d_in, const int* in_sizes, int n_in,
                              void* d_out, int out_size) {
    const float* x      = (const float*)d_in[0];
    const float* qkv_w  = (const float*)d_in[1];
    const float* qkv_b  = (const float*)d_in[2];
    const float* proj_w = (const float*)d_in[3];
    const float* proj_b = (const float*)d_in[4];
    const float* table  = (const float*)d_in[5];
    float* out = (float*)d_out;

    void *qkv_p, *x16_p, *acat_p, *wq_p, *wp_p, *tbl_p;
    cudaGetSymbolAddress(&qkv_p,  g_qkv);
    cudaGetSymbolAddress(&x16_p,  g_x16);
    cudaGetSymbolAddress(&acat_p, g_acat);
    cudaGetSymbolAddress(&wq_p,   g_wq);
    cudaGetSymbolAddress(&wp_p,   g_wp);
    cudaGetSymbolAddress(&tbl_p,  g_tbl);
    __half* qkv  = (__half*)qkv_p;
    __half* x16  = (__half*)x16_p;
    __half* acat = (__half*)acat_p;
    __half* wq   = (__half*)wq_p;
    __half* wp   = (__half*)wp_p;
    __half* tbl  = (__half*)tbl_p;

    static bool attr_done = false;
    if (!attr_done) {
        cudaFuncSetAttribute(gemm_mma<__half>,
                             cudaFuncAttributeMaxDynamicSharedMemorySize,
                             GEMM_SMEM);
        cudaFuncSetAttribute(gemm_mma<float>,
                             cudaFuncAttributeMaxDynamicSharedMemorySize,
                             GEMM_SMEM);
        attr_done = true;
    }

    convert_h<<<(M_ROWS * 64 + 255) / 256, 256>>>(x, x16, M_ROWS * 64);
    convert_h<<<(768 * 64 + 255) / 256, 256>>>(qkv_w, wq, 768 * 64);
    convert_h<<<(256 * 64 + 255) / 256, 256>>>(proj_w, wp, 256 * 64);
    build_tbl<<<32, 256>>>(table, tbl);

    dim3 gq(768 / 128, M_ROWS / 128);
    gemm_mma<__half><<<gq, 256, GEMM_SMEM>>>(x16, wq, qkv_b, qkv, 768);

    attn_mma<<<2048 * 8, 64>>>(qkv, tbl, acat);

    dim3 gp(256 / 128, M_ROWS / 128);
    gemm_mma<float><<<gp, 256, GEMM_SMEM>>>(acat, wp, proj_b, out, 256);
}

// round 13
// speedup vs baseline: 1.1154x; 1.0061x over previous
#include <cuda_runtime.h>
#include <cuda_fp16.h>
#include <cstdint>

// ---------------------------------------------------------------------------
// Swin shifted-window attention, B=32 H=W=56 C=256, 7x7 win, shift 3, 8 heads.
// Plain fp16 GEMMs (K=256), fp32 accumulate. Window-major intermediate layout:
// the roll+window-partition row permutation is folded into the QKV GEMM
// epilogue (forward perm) and the proj GEMM epilogue (inverse perm), so the
// attention kernel reads/writes purely linear rows.
//
//  1) convert x, qkv_w, proj_w -> fp16; build bias+mask table [4][8][64][64]
//  2) QKV GEMM -> g_qkv fp16 [2048*49, 768] (window-major rows)
//  3) attention: per-(window,head) tensor-core MMA, table logits + softmax
//     -> acat fp16 [2048*49, 256] (window-major)
//  4) proj GEMM: d_out[M,256] fp32 (inverse perm in epilogue)
// ---------------------------------------------------------------------------

#define M_ROWS 100352           // 32*56*56 == 2048*49
#define KC     256

__device__ __half g_qkv[100352ULL * 768];
__device__ __half g_x16[100352ULL * 256];
__device__ __half g_acat[100352ULL * 256];
__device__ __half g_wq[768ULL * 256];
__device__ __half g_wp[256ULL * 256];
__device__ __half g_tbl[4 * 8 * 64 * 64];   // bias+mask per (type, head)

// ======================= helpers ============================================
__device__ __forceinline__ uint32_t smem_u32(const void* p) {
    uint32_t a;
    asm("{ .reg .u64 t; cvta.to.shared.u64 t, %1; cvt.u32.u64 %0, t; }"
        : "=r"(a) : "l"(p));
    return a;
}
__device__ __forceinline__ uint32_t h2u(__half2 h) {
    union { __half2 h; uint32_t u; } c;
    c.h = h;
    return c.u;
}
__device__ __forceinline__ void cp16(uint32_t s, const void* g) {
    asm volatile("cp.async.cg.shared.global [%0], [%1], 16;"
                 :: "r"(s), "l"(g) : "memory");
}
#define CP_COMMIT() asm volatile("cp.async.commit_group;" ::: "memory")
#define CP_WAIT1()  asm volatile("cp.async.wait_group 1;" ::: "memory")

__device__ __forceinline__ void ldsm4(uint32_t& r0, uint32_t& r1,
                                      uint32_t& r2, uint32_t& r3, uint32_t a) {
    asm volatile("ldmatrix.sync.aligned.m8n8.x4.shared.b16 {%0,%1,%2,%3}, [%4];"
                 : "=r"(r0), "=r"(r1), "=r"(r2), "=r"(r3) : "r"(a));
}
__device__ __forceinline__ void ldsm4t(uint32_t& r0, uint32_t& r1,
                                       uint32_t& r2, uint32_t& r3, uint32_t a) {
    asm volatile(
        "ldmatrix.sync.aligned.m8n8.x4.trans.shared.b16 {%0,%1,%2,%3}, [%4];"
        : "=r"(r0), "=r"(r1), "=r"(r2), "=r"(r3) : "r"(a));
}
__device__ __forceinline__ void mma16816(float* c, const uint32_t* a,
                                         const uint32_t* b) {
    asm volatile(
        "mma.sync.aligned.m16n8k16.row.col.f32.f16.f16.f32 "
        "{%0,%1,%2,%3}, {%4,%5,%6,%7}, {%8,%9}, {%0,%1,%2,%3};"
        : "+f"(c[0]), "+f"(c[1]), "+f"(c[2]), "+f"(c[3])
        : "r"(a[0]), "r"(a[1]), "r"(a[2]), "r"(a[3]), "r"(b[0]), "r"(b[1]));
}

// row permutations: original <-> window-major (roll folded in)
__device__ __forceinline__ size_t perm_fwd(size_t m) {
    int b = (int)(m / 3136), rem = (int)(m - (size_t)b * 3136);
    int oh = rem / 56, ow = rem - oh * 56;
    int hh = (oh >= 3) ? oh - 3 : oh + 53;
    int vv = (ow >= 3) ? ow - 3 : ow + 53;
    int w7 = hh / 7, v7 = vv / 7;
    int t  = (hh - w7 * 7) * 7 + (vv - v7 * 7);
    return ((size_t)(b * 64 + w7 * 8 + v7)) * 49 + t;
}
__device__ __forceinline__ size_t perm_inv(size_t r) {
    int w = (int)(r / 49), t = (int)(r - (size_t)w * 49);
    int b = w >> 6, wr = (w >> 3) & 7, wc = w & 7;
    int ih = t / 7, iw = t - ih * 7;
    int oh = wr * 7 + ih + 3; if (oh >= 56) oh -= 56;
    int ow = wc * 7 + iw + 3; if (ow >= 56) ow -= 56;
    return (size_t)b * 3136 + oh * 56 + ow;
}

// ======================= fp32 -> fp16 conversion ============================
__global__ void __launch_bounds__(256)
convert_h(const float* __restrict__ in, __half* __restrict__ out, int total4) {
    int t = blockIdx.x * 256 + threadIdx.x;
    if (t >= total4) return;
    float4 v = *(const float4*)(in + (size_t)t * 4);
    *(__half2*)(out + (size_t)t * 4)     = __floats2half2_rn(v.x, v.y);
    *(__half2*)(out + (size_t)t * 4 + 2) = __floats2half2_rn(v.z, v.w);
}

// ======================= bias+mask table build ==============================
__global__ void __launch_bounds__(256)
build_tbl(const float* __restrict__ table, __half* __restrict__ tbl) {
    int type = blockIdx.x >> 3;
    int head = blockIdx.x & 7;
    int wr = (type & 2) ? 7 : 0;
    int wc = (type & 1) ? 7 : 0;
    for (int idx = threadIdx.x; idx < 4096; idx += 256) {
        int i = idx >> 6, j = idx & 63;
        float v;
        if (j >= 49)      v = -1e4f;
        else if (i >= 49) v = 0.f;
        else {
            int ih = i / 7, iw = i - ih * 7;
            int jh = j / 7, jw = j - jh * 7;
            float bias = table[((ih - jh + 6) * 13 + (iw - jw + 6)) * 8 + head];
            int hh = wr * 7 + ih, vv = wc * 7 + iw;
            int hj = wr * 7 + jh, wj = wc * 7 + jw;
            int ri = ((hh < 49) ? 0 : (hh < 53 ? 1 : 2)) * 3 +
                     ((vv < 49) ? 0 : (vv < 53 ? 1 : 2));
            int rj = ((hj < 49) ? 0 : (hj < 53 ? 1 : 2)) * 3 +
                     ((wj < 49) ? 0 : (wj < 53 ? 1 : 2));
            v = bias + ((ri != rj) ? -100.f : 0.f);
        }
        tbl[(size_t)blockIdx.x * 4096 + idx] = __float2half_rn(v);
    }
}

// ======================= mma.sync GEMM (BK=64, 3-stage) =====================
// C[M,N] = A[M,256] @ W[N,256]^T + bias. CTA 128x128, 8 warps (4x2),
// warp tile 32x64. PERM: 0=none, 1=forward (C rows permuted to window-major),
// 2=inverse (A rows window-major, C rows original layout).
#define MROW   144
#define MAT_ST (128 * MROW)
#define ST     (2 * MAT_ST)
#define NSTG   3
#define GEMM_SMEM (NSTG * ST)         // 110592 B

template <typename OT, int PERM>
__global__ void __launch_bounds__(256, 2)
gemm_mma(const __half* __restrict__ A, const __half* __restrict__ W,
         const float* __restrict__ bias, OT* __restrict__ C, int N) {
    extern __shared__ __half smbuf[];

    const int tid  = threadIdx.x;
    const int wid  = tid >> 5;
    const int lane = tid & 31;
    const int wm   = wid & 3;
    const int wn   = wid >> 2;
    const size_t m0 = (size_t)blockIdx.y * 128;
    const int    n0 = blockIdx.x * 128;
    const uint32_t s0 = smem_u32(smbuf);

    float acc[2][8][4];
#pragma unroll
    for (int i = 0; i < 2; i++)
#pragma unroll
        for (int j = 0; j < 8; j++)
#pragma unroll
            for (int k = 0; k < 4; k++) acc[i][j][k] = 0.f;

    const __half* gA = A + m0 * KC;
    const __half* gB = W + (size_t)n0 * KC;

#define LOAD_SLAB(st, slab)                                                  \
    do {                                                                     \
        uint32_t ab_ = s0 + (st) * ST;                                       \
        uint32_t bb_ = ab_ + MAT_ST;                                         \
        int k0_ = (slab) * 64;                                               \
        _Pragma("unroll")                                                    \
        for (int i_ = 0; i_ < 4; i_++) {                                     \
            int seg_ = tid + i_ * 256;                                       \
            int r_ = seg_ >> 3, c_ = seg_ & 7;                               \
            uint32_t so_ = r_ * MROW + c_ * 16;                              \
            cp16(ab_ + so_, gA + (size_t)r_ * KC + k0_ + c_ * 8);            \
            cp16(bb_ + so_, gB + (size_t)r_ * KC + k0_ + c_ * 8);            \
        }                                                                    \
    } while (0)

    const int NS = KC / 64;

    LOAD_SLAB(0, 0); CP_COMMIT();
    LOAD_SLAB(1, 1); CP_COMMIT();

    const int aRow = wm * 32 + (lane & 15);
    const int aChk = lane >> 4;
    const int bRowBase = wn * 64 + (lane & 7) + ((lane >> 4) << 3);
    const int bChk = (lane >> 3) & 1;

    for (int f = 0; f < NS; f++) {
        CP_WAIT1();
        __syncthreads();

        const int st = (f < 3) ? f : 0;
        const uint32_t aBase = s0 + st * ST;
        const uint32_t bBase = aBase + MAT_ST;
#pragma unroll
        for (int kk = 0; kk < 4; kk++) {
            uint32_t af[2][4];
#pragma unroll
            for (int mt = 0; mt < 2; mt++) {
                uint32_t ad = aBase + (aRow + mt * 16) * MROW +
                              (kk * 2 + aChk) * 16;
                ldsm4(af[mt][0], af[mt][1], af[mt][2], af[mt][3], ad);
            }
            uint32_t bf[8][2];
#pragma unroll
            for (int pr = 0; pr < 4; pr++) {
                uint32_t bd = bBase + (bRowBase + pr * 16) * MROW +
                              (kk * 2 + bChk) * 16;
                uint32_t r0, r1, r2, r3;
                ldsm4(r0, r1, r2, r3, bd);
                bf[2 * pr][0] = r0; bf[2 * pr][1] = r1;
                bf[2 * pr + 1][0] = r2; bf[2 * pr + 1][1] = r3;
            }
#pragma unroll
            for (int mt = 0; mt < 2; mt++)
#pragma unroll
                for (int nt = 0; nt < 8; nt++)
                    mma16816(acc[mt][nt], af[mt], bf[nt]);
        }

        if (f + 2 < NS) {
            int st2 = f + 2 - 3 < 0 ? f + 2 : f - 1;
            LOAD_SLAB(st2, f + 2);
        }
        CP_COMMIT();
    }

    const int g  = lane >> 2;
    const int t4 = lane & 3;

    // destination rows (with optional permutation)
    size_t prow[2][2];
#pragma unroll
    for (int mt = 0; mt < 2; mt++)
#pragma unroll
        for (int hh = 0; hh < 2; hh++) {
            size_t r = m0 + wm * 32 + mt * 16 + g + 8 * hh;
            if (PERM == 1)      r = perm_fwd(r);
            else if (PERM == 2) r = perm_inv(r);
            prow[mt][hh] = r;
        }

#pragma unroll
    for (int nt = 0; nt < 8; nt++) {
        const int col = n0 + wn * 64 + nt * 8 + 2 * t4;
        float2 bb = *(const float2*)(bias + col);
#pragma unroll
        for (int mt = 0; mt < 2; mt++) {
            float v00 = acc[mt][nt][0] + bb.x, v01 = acc[mt][nt][1] + bb.y;
            float v10 = acc[mt][nt][2] + bb.x, v11 = acc[mt][nt][3] + bb.y;
            if constexpr (sizeof(OT) == 4) {
                *(float2*)((float*)C + prow[mt][0] * N + col) =
                    make_float2(v00, v01);
                *(float2*)((float*)C + prow[mt][1] * N + col) =
                    make_float2(v10, v11);
            } else {
                *(__half2*)((__half*)C + prow[mt][0] * N + col) =
                    __floats2half2_rn(v00, v01);
                *(__half2*)((__half*)C + prow[mt][1] * N + col) =
                    __floats2half2_rn(v10, v11);
            }
        }
    }
#undef LOAD_SLAB
}

// ======================= tensor-core attention ==============================
// Block = (window, head), 64 threads (2 warps). Rows are linear (window-major).
__global__ void __launch_bounds__(64)
attn_mma(const __half* __restrict__ qkv, const __half* __restrict__ tblg,
         __half* __restrict__ outp) {
    __shared__ __align__(16) __half Qs[64 * 40];
    __shared__ __align__(16) __half Ks[64 * 40];
    __shared__ __align__(16) __half Vs[64 * 40];
    __shared__ __align__(16) __half Ts[64 * 72];

    const int tid  = threadIdx.x;
    const int w    = tid >> 5;
    const int lane = tid & 31;
    const int head = blockIdx.x & 7;
    const int win  = blockIdx.x >> 3;
    const int wr   = (win >> 3) & 7;
    const int wc   = win & 7;
    const size_t base = (size_t)win * 49;

    // stage bias+mask table (4096 halves = 512 uint4)
    {
        const int type = ((wr == 7) ? 2 : 0) | ((wc == 7) ? 1 : 0);
        const uint4* Tg = (const uint4*)(tblg + (size_t)(type * 8 + head) * 4096);
        for (int idx = tid; idx < 512; idx += 64) {
            int r = idx >> 3, c = idx & 7;
            *(uint4*)(Ts + r * 72 + c * 8) = Tg[idx];
        }
    }
    // zero pad rows 49..63 of Q,K,V
    for (int idx = tid; idx < 180; idx += 64) {
        int mat = idx / 60, rem = idx - mat * 60;
        int r = 49 + (rem >> 2), q = rem & 3;
        __half* bp = (mat == 0) ? Qs : (mat == 1) ? Ks : Vs;
        *(uint4*)(bp + r * 40 + q * 8) = make_uint4(0, 0, 0, 0);
    }

    // linear gather: rows base..base+48
    for (int idx = tid; idx < 196; idx += 64) {
        int p = idx >> 2, q = idx & 3;
        const __half* src = qkv + (base + p) * 768 + head * 32 + q * 8;
        *(uint4*)(Qs + p * 40 + q * 8) = *(const uint4*)(src);
        *(uint4*)(Ks + p * 40 + q * 8) = *(const uint4*)(src + 256);
        *(uint4*)(Vs + p * 40 + q * 8) = *(const uint4*)(src + 512);
    }
    __syncthreads();

    const uint32_t sQ = smem_u32(Qs), sK = smem_u32(Ks), sV = smem_u32(Vs);

    // ---- S = Q K^T ----
    uint32_t aQ[2][2][4];
#pragma unroll
    for (int mt = 0; mt < 2; mt++)
#pragma unroll
        for (int kk = 0; kk < 2; kk++) {
            int row = w * 32 + mt * 16 + (lane & 15);
            uint32_t ad = sQ + row * 80 + (kk * 2 + (lane >> 4)) * 16;
            ldsm4(aQ[mt][kk][0], aQ[mt][kk][1], aQ[mt][kk][2], aQ[mt][kk][3], ad);
        }
    uint32_t bK[2][8][2];
#pragma unroll
    for (int kk = 0; kk < 2; kk++)
#pragma unroll
        for (int pr = 0; pr < 4; pr++) {
            int row = pr * 16 + (lane & 7) + ((lane >> 4) << 3);
            uint32_t ad = sK + row * 80 + (kk * 2 + ((lane >> 3) & 1)) * 16;
            uint32_t r0, r1, r2, r3;
            ldsm4(r0, r1, r2, r3, ad);
            bK[kk][2 * pr][0] = r0;     bK[kk][2 * pr][1] = r1;
            bK[kk][2 * pr + 1][0] = r2; bK[kk][2 * pr + 1][1] = r3;
        }
    float s[2][8][4];
#pragma unroll
    for (int mt = 0; mt < 2; mt++)
#pragma unroll
        for (int nt = 0; nt < 8; nt++) {
            s[mt][nt][0] = s[mt][nt][1] = s[mt][nt][2] = s[mt][nt][3] = 0.f;
            mma16816(s[mt][nt], aQ[mt][0], bK[0][nt]);
            mma16816(s[mt][nt], aQ[mt][1], bK[1][nt]);
        }

    const int g  = lane >> 2;
    const int t4 = lane & 3;
    const float scale = 0.17677669529663687f;

    // ---- logits: s*scale + table ----
#pragma unroll
    for (int mt = 0; mt < 2; mt++)
#pragma unroll
        for (int h = 0; h < 2; h++) {
            const __half* trow = Ts + (w * 32 + mt * 16 + g + 8 * h) * 72;
#pragma unroll
            for (int nt = 0; nt < 8; nt++) {
                __half2 t2 = *(const __half2*)(trow + nt * 8 + 2 * t4);
                float2 tf = __half22float2(t2);
                s[mt][nt][2 * h]     = fmaf(s[mt][nt][2 * h],     scale, tf.x);
                s[mt][nt][2 * h + 1] = fmaf(s[mt][nt][2 * h + 1], scale, tf.y);
            }
        }

    // ---- softmax ----
    float zinv[2][2];
#pragma unroll
    for (int mt = 0; mt < 2; mt++)
#pragma unroll
        for (int h = 0; h < 2; h++) {
            float m = -1e30f;
#pragma unroll
            for (int nt = 0; nt < 8; nt++) {
                m = fmaxf(m, s[mt][nt][2 * h]);
                m = fmaxf(m, s[mt][nt][2 * h + 1]);
            }
            m = fmaxf(m, __shfl_xor_sync(0xffffffffu, m, 1));
            m = fmaxf(m, __shfl_xor_sync(0xffffffffu, m, 2));
            float sum = 0.f;
#pragma unroll
            for (int nt = 0; nt < 8; nt++) {
                float e0 = __expf(s[mt][nt][2 * h] - m);
                float e1 = __expf(s[mt][nt][2 * h + 1] - m);
                s[mt][nt][2 * h] = e0;
                s[mt][nt][2 * h + 1] = e1;
                sum += e0 + e1;
            }
            sum += __shfl_xor_sync(0xffffffffu, sum, 1);
            sum += __shfl_xor_sync(0xffffffffu, sum, 2);
            zinv[mt][h] = 1.0f / sum;
        }

    uint32_t aP[2][4][4];
#pragma unroll
    for (int mt = 0; mt < 2; mt++)
#pragma unroll
        for (int kt = 0; kt < 4; kt++) {
            aP[mt][kt][0] = h2u(__floats2half2_rn(s[mt][2 * kt][0],
                                                  s[mt][2 * kt][1]));
            aP[mt][kt][1] = h2u(__floats2half2_rn(s[mt][2 * kt][2],
                                                  s[mt][2 * kt][3]));
            aP[mt][kt][2] = h2u(__floats2half2_rn(s[mt][2 * kt + 1][0],
                                                  s[mt][2 * kt + 1][1]));
            aP[mt][kt][3] = h2u(__floats2half2_rn(s[mt][2 * kt + 1][2],
                                                  s[mt][2 * kt + 1][3]));
        }

    uint32_t bV[4][4][2];
#pragma unroll
    for (int kt = 0; kt < 4; kt++)
#pragma unroll
        for (int nh = 0; nh < 2; nh++) {
            int row = kt * 16 + (lane & 7) + (((lane >> 3) & 1) << 3);
            uint32_t ad = sV + row * 80 + nh * 32 + ((lane >> 4) << 4);
            uint32_t r0, r1, r2, r3;
            ldsm4t(r0, r1, r2, r3, ad);
            bV[kt][2 * nh][0] = r0;     bV[kt][2 * nh][1] = r1;
            bV[kt][2 * nh + 1][0] = r2; bV[kt][2 * nh + 1][1] = r3;
        }

    float o[2][4][4];
#pragma unroll
    for (int mt = 0; mt < 2; mt++)
#pragma unroll
        for (int vn = 0; vn < 4; vn++) {
            o[mt][vn][0] = o[mt][vn][1] = o[mt][vn][2] = o[mt][vn][3] = 0.f;
#pragma unroll
            for (int kt = 0; kt < 4; kt++)
                mma16816(o[mt][vn], aP[mt][kt], bV[kt][vn]);
        }

#pragma unroll
    for (int mt = 0; mt < 2; mt++)
#pragma unroll
        for (int h = 0; h < 2; h++) {
            int i = w * 32 + mt * 16 + g + 8 * h;
            if (i >= 49) continue;
            float rz = zinv[mt][h];
            __half* dst = outp + (base + i) * KC + head * 32;
#pragma unroll
            for (int vn = 0; vn < 4; vn++) {
                int col = vn * 8 + 2 * t4;
                *(__half2*)(dst + col) =
                    __floats2half2_rn(o[mt][vn][2 * h] * rz,
                                      o[mt][vn][2 * h + 1] * rz);
            }
        }
}

// ---------------------------------------------------------------------------
extern "C" void kernel_launch(void* const* d_in, const int* in_sizes, int n_in,
                              void* d_out, int out_size) {
    const float* x      = (const float*)d_in[0];
    const float* qkv_w  = (const float*)d_in[1];
    const float* qkv_b  = (const float*)d_in[2];
    const float* proj_w = (const float*)d_in[3];
    const float* proj_b = (const float*)d_in[4];
    const float* table  = (const float*)d_in[5];
    float* out = (float*)d_out;

    void *qkv_p, *x16_p, *acat_p, *wq_p, *wp_p, *tbl_p;
    cudaGetSymbolAddress(&qkv_p,  g_qkv);
    cudaGetSymbolAddress(&x16_p,  g_x16);
    cudaGetSymbolAddress(&acat_p, g_acat);
    cudaGetSymbolAddress(&wq_p,   g_wq);
    cudaGetSymbolAddress(&wp_p,   g_wp);
    cudaGetSymbolAddress(&tbl_p,  g_tbl);
    __half* qkv  = (__half*)qkv_p;
    __half* x16  = (__half*)x16_p;
    __half* acat = (__half*)acat_p;
    __half* wq   = (__half*)wq_p;
    __half* wp   = (__half*)wp_p;
    __half* tbl  = (__half*)tbl_p;

    static bool attr_done = false;
    if (!attr_done) {
        cudaFuncSetAttribute((const void*)gemm_mma<__half, 1>,
                             cudaFuncAttributeMaxDynamicSharedMemorySize,
                             GEMM_SMEM);
        cudaFuncSetAttribute((const void*)gemm_mma<float, 2>,
                             cudaFuncAttributeMaxDynamicSharedMemorySize,
                             GEMM_SMEM);
        attr_done = true;
    }

    convert_h<<<(M_ROWS * 64 + 255) / 256, 256>>>(x, x16, M_ROWS * 64);
    convert_h<<<(768 * 64 + 255) / 256, 256>>>(qkv_w, wq, 768 * 64);
    convert_h<<<(256 * 64 + 255) / 256, 256>>>(proj_w, wp, 256 * 64);
    build_tbl<<<32, 256>>>(table, tbl);

    dim3 gq(768 / 128, M_ROWS / 128);
    gemm_mma<__half, 1><<<gq, 256, GEMM_SMEM>>>(x16, wq, qkv_b, qkv, 768);

    attn_mma<<<2048 * 8, 64>>>(qkv, tbl, acat);

    dim3 gp(256 / 128, M_ROWS / 128);
    gemm_mma<float, 2><<<gp, 256, GEMM_SMEM>>>(acat, wp, proj_b, out, 256);
}

// round 14
// speedup vs baseline: 1.1564x; 1.0368x over previous
#include <cuda_runtime.h>
#include <cuda_fp16.h>
#include <cstdint>

// ---------------------------------------------------------------------------
// Swin shifted-window attention, B=32 H=W=56 C=256, 7x7 win, shift 3, 8 heads.
// Plain fp16 GEMMs (K=256), fp32 accumulate. Window-major + head-major
// intermediate layouts:
//   g_qkv : [win][mat(q,k,v)][head][49][32]  (QKV GEMM epilogue writes this)
//   g_acat: [win][head][49][32]              (attention writes, proj A reads)
// The roll+window-partition permutation is folded into the QKV epilogue
// (forward) and proj epilogue (inverse).
// ---------------------------------------------------------------------------

#define M_ROWS 100352           // 32*56*56 == 2048*49
#define KC     256

__device__ __half g_qkv[2048ULL * 3 * 8 * 49 * 32];
__device__ __half g_x16[100352ULL * 256];
__device__ __half g_acat[2048ULL * 8 * 49 * 32];
__device__ __half g_wq[768ULL * 256];
__device__ __half g_wp[256ULL * 256];
__device__ __half g_tbl[4 * 8 * 64 * 64];   // bias+mask per (type, head)

// ======================= helpers ============================================
__device__ __forceinline__ uint32_t smem_u32(const void* p) {
    uint32_t a;
    asm("{ .reg .u64 t; cvta.to.shared.u64 t, %1; cvt.u32.u64 %0, t; }"
        : "=r"(a) : "l"(p));
    return a;
}
__device__ __forceinline__ uint32_t h2u(__half2 h) {
    union { __half2 h; uint32_t u; } c;
    c.h = h;
    return c.u;
}
__device__ __forceinline__ void cp16(uint32_t s, const void* g) {
    asm volatile("cp.async.cg.shared.global [%0], [%1], 16;"
                 :: "r"(s), "l"(g) : "memory");
}
#define CP_COMMIT() asm volatile("cp.async.commit_group;" ::: "memory")
#define CP_WAIT1()  asm volatile("cp.async.wait_group 1;" ::: "memory")

__device__ __forceinline__ void ldsm4(uint32_t& r0, uint32_t& r1,
                                      uint32_t& r2, uint32_t& r3, uint32_t a) {
    asm volatile("ldmatrix.sync.aligned.m8n8.x4.shared.b16 {%0,%1,%2,%3}, [%4];"
                 : "=r"(r0), "=r"(r1), "=r"(r2), "=r"(r3) : "r"(a));
}
__device__ __forceinline__ void ldsm4t(uint32_t& r0, uint32_t& r1,
                                       uint32_t& r2, uint32_t& r3, uint32_t a) {
    asm volatile(
        "ldmatrix.sync.aligned.m8n8.x4.trans.shared.b16 {%0,%1,%2,%3}, [%4];"
        : "=r"(r0), "=r"(r1), "=r"(r2), "=r"(r3) : "r"(a));
}
__device__ __forceinline__ void mma16816(float* c, const uint32_t* a,
                                         const uint32_t* b) {
    asm volatile(
        "mma.sync.aligned.m16n8k16.row.col.f32.f16.f16.f32 "
        "{%0,%1,%2,%3}, {%4,%5,%6,%7}, {%8,%9}, {%0,%1,%2,%3};"
        : "+f"(c[0]), "+f"(c[1]), "+f"(c[2]), "+f"(c[3])
        : "r"(a[0]), "r"(a[1]), "r"(a[2]), "r"(a[3]), "r"(b[0]), "r"(b[1]));
}

// forward perm: original row -> window-major row
__device__ __forceinline__ size_t perm_fwd(size_t m) {
    int b = (int)(m / 3136), rem = (int)(m - (size_t)b * 3136);
    int oh = rem / 56, ow = rem - oh * 56;
    int hh = (oh >= 3) ? oh - 3 : oh + 53;
    int vv = (ow >= 3) ? ow - 3 : ow + 53;
    int w7 = hh / 7, v7 = vv / 7;
    int t  = (hh - w7 * 7) * 7 + (vv - v7 * 7);
    return ((size_t)(b * 64 + w7 * 8 + v7)) * 49 + t;
}
// inverse perm: window-major row -> original row
__device__ __forceinline__ size_t perm_inv(size_t r) {
    int w = (int)(r / 49), t = (int)(r - (size_t)w * 49);
    int b = w >> 6, wr = (w >> 3) & 7, wc = w & 7;
    int ih = t / 7, iw = t - ih * 7;
    int oh = wr * 7 + ih + 3; if (oh >= 56) oh -= 56;
    int ow = wc * 7 + iw + 3; if (ow >= 56) ow -= 56;
    return (size_t)b * 3136 + oh * 56 + ow;
}

// ======================= fp32 -> fp16 conversion ============================
__global__ void __launch_bounds__(256)
convert_h(const float* __restrict__ in, __half* __restrict__ out, int total4) {
    int t = blockIdx.x * 256 + threadIdx.x;
    if (t >= total4) return;
    float4 v = *(const float4*)(in + (size_t)t * 4);
    *(__half2*)(out + (size_t)t * 4)     = __floats2half2_rn(v.x, v.y);
    *(__half2*)(out + (size_t)t * 4 + 2) = __floats2half2_rn(v.z, v.w);
}

// ======================= bias+mask table build ==============================
__global__ void __launch_bounds__(256)
build_tbl(const float* __restrict__ table, __half* __restrict__ tbl) {
    int type = blockIdx.x >> 3;
    int head = blockIdx.x & 7;
    int wr = (type & 2) ? 7 : 0;
    int wc = (type & 1) ? 7 : 0;
    for (int idx = threadIdx.x; idx < 4096; idx += 256) {
        int i = idx >> 6, j = idx & 63;
        float v;
        if (j >= 49)      v = -1e4f;
        else if (i >= 49) v = 0.f;
        else {
            int ih = i / 7, iw = i - ih * 7;
            int jh = j / 7, jw = j - jh * 7;
            float bias = table[((ih - jh + 6) * 13 + (iw - jw + 6)) * 8 + head];
            int hh = wr * 7 + ih, vv = wc * 7 + iw;
            int hj = wr * 7 + jh, wj = wc * 7 + jw;
            int ri = ((hh < 49) ? 0 : (hh < 53 ? 1 : 2)) * 3 +
                     ((vv < 49) ? 0 : (vv < 53 ? 1 : 2));
            int rj = ((hj < 49) ? 0 : (hj < 53 ? 1 : 2)) * 3 +
                     ((wj < 49) ? 0 : (wj < 53 ? 1 : 2));
            v = bias + ((ri != rj) ? -100.f : 0.f);
        }
        tbl[(size_t)blockIdx.x * 4096 + idx] = __float2half_rn(v);
    }
}

// ======================= mma.sync GEMM (BK=64, 3-stage) =====================
// PERM=1 (QKV): A row-major [M,256]; C written head-major:
//   dst = (((win*3+mat)*8+head)*49 + t)*32 + d,  row perm_fwd'd.
// PERM=2 (proj): A read from head-major acat [win][head][49][32];
//   C row-major at perm_inv(row).
#define MROW   144
#define MAT_ST (128 * MROW)
#define ST     (2 * MAT_ST)
#define NSTG   3
#define GEMM_SMEM (NSTG * ST)         // 110592 B

template <typename OT, int PERM>
__global__ void __launch_bounds__(256, 2)
gemm_mma(const __half* __restrict__ A, const __half* __restrict__ W,
         const float* __restrict__ bias, OT* __restrict__ C, int N) {
    extern __shared__ __half smbuf[];

    const int tid  = threadIdx.x;
    const int wid  = tid >> 5;
    const int lane = tid & 31;
    const int wm   = wid & 3;
    const int wn   = wid >> 2;
    const size_t m0 = (size_t)blockIdx.y * 128;
    const int    n0 = blockIdx.x * 128;
    const uint32_t s0 = smem_u32(smbuf);

    float acc[2][8][4];
#pragma unroll
    for (int i = 0; i < 2; i++)
#pragma unroll
        for (int j = 0; j < 8; j++)
#pragma unroll
            for (int k = 0; k < 4; k++) acc[i][j][k] = 0.f;

    const __half* gA = A + m0 * KC;
    const __half* gB = W + (size_t)n0 * KC;

#define LOAD_SLAB(st, slab)                                                  \
    do {                                                                     \
        uint32_t ab_ = s0 + (st) * ST;                                       \
        uint32_t bb_ = ab_ + MAT_ST;                                         \
        int k0_ = (slab) * 64;                                               \
        _Pragma("unroll")                                                    \
        for (int i_ = 0; i_ < 4; i_++) {                                     \
            int seg_ = tid + i_ * 256;                                       \
            int r_ = seg_ >> 3, c_ = seg_ & 7;                               \
            uint32_t so_ = r_ * MROW + c_ * 16;                              \
            const __half* asrc_;                                             \
            if (PERM == 2) {                                                 \
                int m_ = (int)(m0) + r_;                                     \
                int win_ = m_ / 49, t_ = m_ - win_ * 49;                     \
                int head_ = (k0_ >> 5) + (c_ >> 2);                          \
                asrc_ = A + (((size_t)win_ * 8 + head_) * 49 + t_) * 32 +    \
                        (c_ & 3) * 8;                                        \
            } else {                                                         \
                asrc_ = gA + (size_t)r_ * KC + k0_ + c_ * 8;                 \
            }                                                                \
            cp16(ab_ + so_, asrc_);                                          \
            cp16(bb_ + so_, gB + (size_t)r_ * KC + k0_ + c_ * 8);            \
        }                                                                    \
    } while (0)

    const int NS = KC / 64;

    LOAD_SLAB(0, 0); CP_COMMIT();
    LOAD_SLAB(1, 1); CP_COMMIT();

    const int aRow = wm * 32 + (lane & 15);
    const int aChk = lane >> 4;
    const int bRowBase = wn * 64 + (lane & 7) + ((lane >> 4) << 3);
    const int bChk = (lane >> 3) & 1;

    for (int f = 0; f < NS; f++) {
        CP_WAIT1();
        __syncthreads();

        const int st = (f < 3) ? f : 0;
        const uint32_t aBase = s0 + st * ST;
        const uint32_t bBase = aBase + MAT_ST;
#pragma unroll
        for (int kk = 0; kk < 4; kk++) {
            uint32_t af[2][4];
#pragma unroll
            for (int mt = 0; mt < 2; mt++) {
                uint32_t ad = aBase + (aRow + mt * 16) * MROW +
                              (kk * 2 + aChk) * 16;
                ldsm4(af[mt][0], af[mt][1], af[mt][2], af[mt][3], ad);
            }
            uint32_t bf[8][2];
#pragma unroll
            for (int pr = 0; pr < 4; pr++) {
                uint32_t bd = bBase + (bRowBase + pr * 16) * MROW +
                              (kk * 2 + bChk) * 16;
                uint32_t r0, r1, r2, r3;
                ldsm4(r0, r1, r2, r3, bd);
                bf[2 * pr][0] = r0; bf[2 * pr][1] = r1;
                bf[2 * pr + 1][0] = r2; bf[2 * pr + 1][1] = r3;
            }
#pragma unroll
            for (int mt = 0; mt < 2; mt++)
#pragma unroll
                for (int nt = 0; nt < 8; nt++)
                    mma16816(acc[mt][nt], af[mt], bf[nt]);
        }

        if (f + 2 < NS) {
            int st2 = f + 2 - 3 < 0 ? f + 2 : f - 1;
            LOAD_SLAB(st2, f + 2);
        }
        CP_COMMIT();
    }

    const int g  = lane >> 2;
    const int t4 = lane & 3;

    // destination rows
    size_t prow[2][2];
    int pwin[2][2], pt[2][2];
#pragma unroll
    for (int mt = 0; mt < 2; mt++)
#pragma unroll
        for (int hh = 0; hh < 2; hh++) {
            size_t r = m0 + wm * 32 + mt * 16 + g + 8 * hh;
            if (PERM == 1) {
                r = perm_fwd(r);
                pwin[mt][hh] = (int)(r / 49);
                pt[mt][hh]   = (int)(r - (size_t)pwin[mt][hh] * 49);
            } else if (PERM == 2) {
                r = perm_inv(r);
            }
            prow[mt][hh] = r;
        }

#pragma unroll
    for (int nt = 0; nt < 8; nt++) {
        const int col = n0 + wn * 64 + nt * 8 + 2 * t4;
        float2 bb = *(const float2*)(bias + col);
#pragma unroll
        for (int mt = 0; mt < 2; mt++) {
            float v00 = acc[mt][nt][0] + bb.x, v01 = acc[mt][nt][1] + bb.y;
            float v10 = acc[mt][nt][2] + bb.x, v11 = acc[mt][nt][3] + bb.y;
            if constexpr (PERM == 1) {
                // head-major qkv: (((win*3+mat)*8+head)*49 + t)*32 + d
                int mat  = col >> 8;
                int head = (col & 255) >> 5;
                int d    = col & 31;
#pragma unroll
                for (int hh = 0; hh < 2; hh++) {
                    size_t off = (((size_t)pwin[mt][hh] * 3 + mat) * 8 + head)
                                     * 1568 + pt[mt][hh] * 32 + d;
                    float a0 = hh ? v10 : v00, a1 = hh ? v11 : v01;
                    *(__half2*)((__half*)C + off) = __floats2half2_rn(a0, a1);
                }
            } else if constexpr (sizeof(OT) == 4) {
                *(float2*)((float*)C + prow[mt][0] * N + col) =
                    make_float2(v00, v01);
                *(float2*)((float*)C + prow[mt][1] * N + col) =
                    make_float2(v10, v11);
            } else {
                *(__half2*)((__half*)C + prow[mt][0] * N + col) =
                    __floats2half2_rn(v00, v01);
                *(__half2*)((__half*)C + prow[mt][1] * N + col) =
                    __floats2half2_rn(v10, v11);
            }
        }
    }
#undef LOAD_SLAB
}

// ======================= tensor-core attention ==============================
// Block = (window, head), 64 threads. Q/K/V contiguous 3136B chunks.
__global__ void __launch_bounds__(64)
attn_mma(const __half* __restrict__ qkv, const __half* __restrict__ tblg,
         __half* __restrict__ outp) {
    __shared__ __align__(16) __half Qs[64 * 40];
    __shared__ __align__(16) __half Ks[64 * 40];
    __shared__ __align__(16) __half Vs[64 * 40];
    __shared__ __align__(16) __half Ts[64 * 72];

    const int tid  = threadIdx.x;
    const int w    = tid >> 5;
    const int lane = tid & 31;
    const int head = blockIdx.x & 7;
    const int win  = blockIdx.x >> 3;
    const int wr   = (win >> 3) & 7;
    const int wc   = win & 7;

    // stage bias+mask table
    {
        const int type = ((wr == 7) ? 2 : 0) | ((wc == 7) ? 1 : 0);
        const uint4* Tg = (const uint4*)(tblg + (size_t)(type * 8 + head) * 4096);
        for (int idx = tid; idx < 512; idx += 64) {
            int r = idx >> 3, c = idx & 7;
            *(uint4*)(Ts + r * 72 + c * 8) = Tg[idx];
        }
    }
    // zero pad rows 49..63
    for (int idx = tid; idx < 180; idx += 64) {
        int mat = idx / 60, rem = idx - mat * 60;
        int r = 49 + (rem >> 2), q = rem & 3;
        __half* bp = (mat == 0) ? Qs : (mat == 1) ? Ks : Vs;
        *(uint4*)(bp + r * 40 + q * 8) = make_uint4(0, 0, 0, 0);
    }

    // contiguous gather: per matrix 1568 halves = 196 uint4
    {
        const __half* srcQ = qkv + ((size_t)win * 24 + head) * 1568;
        const __half* srcK = srcQ + 8 * 1568;
        const __half* srcV = srcQ + 16 * 1568;
        for (int idx = tid; idx < 196; idx += 64) {
            int p = idx >> 2, q = idx & 3;
            int off = p * 32 + q * 8;
            *(uint4*)(Qs + p * 40 + q * 8) = *(const uint4*)(srcQ + off);
            *(uint4*)(Ks + p * 40 + q * 8) = *(const uint4*)(srcK + off);
            *(uint4*)(Vs + p * 40 + q * 8) = *(const uint4*)(srcV + off);
        }
    }
    __syncthreads();

    const uint32_t sQ = smem_u32(Qs), sK = smem_u32(Ks), sV = smem_u32(Vs);

    // ---- S = Q K^T ----
    uint32_t aQ[2][2][4];
#pragma unroll
    for (int mt = 0; mt < 2; mt++)
#pragma unroll
        for (int kk = 0; kk < 2; kk++) {
            int row = w * 32 + mt * 16 + (lane & 15);
            uint32_t ad = sQ + row * 80 + (kk * 2 + (lane >> 4)) * 16;
            ldsm4(aQ[mt][kk][0], aQ[mt][kk][1], aQ[mt][kk][2], aQ[mt][kk][3], ad);
        }
    uint32_t bK[2][8][2];
#pragma unroll
    for (int kk = 0; kk < 2; kk++)
#pragma unroll
        for (int pr = 0; pr < 4; pr++) {
            int row = pr * 16 + (lane & 7) + ((lane >> 4) << 3);
            uint32_t ad = sK + row * 80 + (kk * 2 + ((lane >> 3) & 1)) * 16;
            uint32_t r0, r1, r2, r3;
            ldsm4(r0, r1, r2, r3, ad);
            bK[kk][2 * pr][0] = r0;     bK[kk][2 * pr][1] = r1;
            bK[kk][2 * pr + 1][0] = r2; bK[kk][2 * pr + 1][1] = r3;
        }
    float s[2][8][4];
#pragma unroll
    for (int mt = 0; mt < 2; mt++)
#pragma unroll
        for (int nt = 0; nt < 8; nt++) {
            s[mt][nt][0] = s[mt][nt][1] = s[mt][nt][2] = s[mt][nt][3] = 0.f;
            mma16816(s[mt][nt], aQ[mt][0], bK[0][nt]);
            mma16816(s[mt][nt], aQ[mt][1], bK[1][nt]);
        }

    const int g  = lane >> 2;
    const int t4 = lane & 3;
    const float scale = 0.17677669529663687f;

    // ---- logits ----
#pragma unroll
    for (int mt = 0; mt < 2; mt++)
#pragma unroll
        for (int h = 0; h < 2; h++) {
            const __half* trow = Ts + (w * 32 + mt * 16 + g + 8 * h) * 72;
#pragma unroll
            for (int nt = 0; nt < 8; nt++) {
                __half2 t2 = *(const __half2*)(trow + nt * 8 + 2 * t4);
                float2 tf = __half22float2(t2);
                s[mt][nt][2 * h]     = fmaf(s[mt][nt][2 * h],     scale, tf.x);
                s[mt][nt][2 * h + 1] = fmaf(s[mt][nt][2 * h + 1], scale, tf.y);
            }
        }

    // ---- softmax ----
    float zinv[2][2];
#pragma unroll
    for (int mt = 0; mt < 2; mt++)
#pragma unroll
        for (int h = 0; h < 2; h++) {
            float m = -1e30f;
#pragma unroll
            for (int nt = 0; nt < 8; nt++) {
                m = fmaxf(m, s[mt][nt][2 * h]);
                m = fmaxf(m, s[mt][nt][2 * h + 1]);
            }
            m = fmaxf(m, __shfl_xor_sync(0xffffffffu, m, 1));
            m = fmaxf(m, __shfl_xor_sync(0xffffffffu, m, 2));
            float sum = 0.f;
#pragma unroll
            for (int nt = 0; nt < 8; nt++) {
                float e0 = __expf(s[mt][nt][2 * h] - m);
                float e1 = __expf(s[mt][nt][2 * h + 1] - m);
                s[mt][nt][2 * h] = e0;
                s[mt][nt][2 * h + 1] = e1;
                sum += e0 + e1;
            }
            sum += __shfl_xor_sync(0xffffffffu, sum, 1);
            sum += __shfl_xor_sync(0xffffffffu, sum, 2);
            zinv[mt][h] = 1.0f / sum;
        }

    uint32_t aP[2][4][4];
#pragma unroll
    for (int mt = 0; mt < 2; mt++)
#pragma unroll
        for (int kt = 0; kt < 4; kt++) {
            aP[mt][kt][0] = h2u(__floats2half2_rn(s[mt][2 * kt][0],
                                                  s[mt][2 * kt][1]));
            aP[mt][kt][1] = h2u(__floats2half2_rn(s[mt][2 * kt][2],
                                                  s[mt][2 * kt][3]));
            aP[mt][kt][2] = h2u(__floats2half2_rn(s[mt][2 * kt + 1][0],
                                                  s[mt][2 * kt + 1][1]));
            aP[mt][kt][3] = h2u(__floats2half2_rn(s[mt][2 * kt + 1][2],
                                                  s[mt][2 * kt + 1][3]));
        }

    uint32_t bV[4][4][2];
#pragma unroll
    for (int kt = 0; kt < 4; kt++)
#pragma unroll
        for (int nh = 0; nh < 2; nh++) {
            int row = kt * 16 + (lane & 7) + (((lane >> 3) & 1) << 3);
            uint32_t ad = sV + row * 80 + nh * 32 + ((lane >> 4) << 4);
            uint32_t r0, r1, r2, r3;
            ldsm4t(r0, r1, r2, r3, ad);
            bV[kt][2 * nh][0] = r0;     bV[kt][2 * nh][1] = r1;
            bV[kt][2 * nh + 1][0] = r2; bV[kt][2 * nh + 1][1] = r3;
        }

    float o[2][4][4];
#pragma unroll
    for (int mt = 0; mt < 2; mt++)
#pragma unroll
        for (int vn = 0; vn < 4; vn++) {
            o[mt][vn][0] = o[mt][vn][1] = o[mt][vn][2] = o[mt][vn][3] = 0.f;
#pragma unroll
            for (int kt = 0; kt < 4; kt++)
                mma16816(o[mt][vn], aP[mt][kt], bV[kt][vn]);
        }

    // ---- store: acat [win][head][49][32] ----
    __half* obase = outp + ((size_t)win * 8 + head) * 1568;
#pragma unroll
    for (int mt = 0; mt < 2; mt++)
#pragma unroll
        for (int h = 0; h < 2; h++) {
            int i = w * 32 + mt * 16 + g + 8 * h;
            if (i >= 49) continue;
            float rz = zinv[mt][h];
            __half* dst = obase + i * 32;
#pragma unroll
            for (int vn = 0; vn < 4; vn++) {
                int col = vn * 8 + 2 * t4;
                *(__half2*)(dst + col) =
                    __floats2half2_rn(o[mt][vn][2 * h] * rz,
                                      o[mt][vn][2 * h + 1] * rz);
            }
        }
}

// ---------------------------------------------------------------------------
extern "C" void kernel_launch(void* const* d_in, const int* in_sizes, int n_in,
                              void* d_out, int out_size) {
    const float* x      = (const float*)d_in[0];
    const float* qkv_w  = (const float*)d_in[1];
    const float* qkv_b  = (const float*)d_in[2];
    const float* proj_w = (const float*)d_in[3];
    const float* proj_b = (const float*)d_in[4];
    const float* table  = (const float*)d_in[5];
    float* out = (float*)d_out;

    void *qkv_p, *x16_p, *acat_p, *wq_p, *wp_p, *tbl_p;
    cudaGetSymbolAddress(&qkv_p,  g_qkv);
    cudaGetSymbolAddress(&x16_p,  g_x16);
    cudaGetSymbolAddress(&acat_p, g_acat);
    cudaGetSymbolAddress(&wq_p,   g_wq);
    cudaGetSymbolAddress(&wp_p,   g_wp);
    cudaGetSymbolAddress(&tbl_p,  g_tbl);
    __half* qkv  = (__half*)qkv_p;
    __half* x16  = (__half*)x16_p;
    __half* acat = (__half*)acat_p;
    __half* wq   = (__half*)wq_p;
    __half* wp   = (__half*)wp_p;
    __half* tbl  = (__half*)tbl_p;

    static bool attr_done = false;
    if (!attr_done) {
        cudaFuncSetAttribute((const void*)gemm_mma<__half, 1>,
                             cudaFuncAttributeMaxDynamicSharedMemorySize,
                             GEMM_SMEM);
        cudaFuncSetAttribute((const void*)gemm_mma<float, 2>,
                             cudaFuncAttributeMaxDynamicSharedMemorySize,
                             GEMM_SMEM);
        attr_done = true;
    }

    convert_h<<<(M_ROWS * 64 + 255) / 256, 256>>>(x, x16, M_ROWS * 64);
    convert_h<<<(768 * 64 + 255) / 256, 256>>>(qkv_w, wq, 768 * 64);
    convert_h<<<(256 * 64 + 255) / 256, 256>>>(proj_w, wp, 256 * 64);
    build_tbl<<<32, 256>>>(table, tbl);

    dim3 gq(768 / 128, M_ROWS / 128);
    gemm_mma<__half, 1><<<gq, 256, GEMM_SMEM>>>(x16, wq, qkv_b, qkv, 768);

    attn_mma<<<2048 * 8, 64>>>(qkv, tbl, acat);

    dim3 gp(256 / 128, M_ROWS / 128);
    gemm_mma<float, 2><<<gp, 256, GEMM_SMEM>>>(acat, wp, proj_b, out, 256);
}

// round 15
// speedup vs baseline: 1.2050x; 1.0420x over previous
#include <cuda_runtime.h>
#include <cuda_fp16.h>
#include <cstdint>

// ---------------------------------------------------------------------------
// Swin shifted-window attention, B=32 H=W=56 C=256, 7x7 win, shift 3, 8 heads.
// Plain fp16 GEMMs (K=256), fp32 accumulate. Head-major intermediates:
//   g_qkv : [win][mat(q,k,v)][head][49][32]
//   g_acat: [win][head][49][32]
// Roll+window permutation folded into GEMM epilogues, which are smem-staged
// for coalesced 16B stores.
// ---------------------------------------------------------------------------

#define M_ROWS 100352           // 32*56*56 == 2048*49
#define KC     256

__device__ __half g_qkv[2048ULL * 3 * 8 * 49 * 32];
__device__ __half g_x16[100352ULL * 256];
__device__ __half g_acat[2048ULL * 8 * 49 * 32];
__device__ __half g_wq[768ULL * 256];
__device__ __half g_wp[256ULL * 256];
__device__ __half g_tbl[4 * 8 * 64 * 64];

// ======================= helpers ============================================
__device__ __forceinline__ uint32_t smem_u32(const void* p) {
    uint32_t a;
    asm("{ .reg .u64 t; cvta.to.shared.u64 t, %1; cvt.u32.u64 %0, t; }"
        : "=r"(a) : "l"(p));
    return a;
}
__device__ __forceinline__ uint32_t h2u(__half2 h) {
    union { __half2 h; uint32_t u; } c;
    c.h = h;
    return c.u;
}
__device__ __forceinline__ void cp16(uint32_t s, const void* g) {
    asm volatile("cp.async.cg.shared.global [%0], [%1], 16;"
                 :: "r"(s), "l"(g) : "memory");
}
#define CP_COMMIT() asm volatile("cp.async.commit_group;" ::: "memory")
#define CP_WAIT1()  asm volatile("cp.async.wait_group 1;" ::: "memory")
#define CP_WAIT0()  asm volatile("cp.async.wait_group 0;" ::: "memory")

__device__ __forceinline__ void ldsm4(uint32_t& r0, uint32_t& r1,
                                      uint32_t& r2, uint32_t& r3, uint32_t a) {
    asm volatile("ldmatrix.sync.aligned.m8n8.x4.shared.b16 {%0,%1,%2,%3}, [%4];"
                 : "=r"(r0), "=r"(r1), "=r"(r2), "=r"(r3) : "r"(a));
}
__device__ __forceinline__ void ldsm4t(uint32_t& r0, uint32_t& r1,
                                       uint32_t& r2, uint32_t& r3, uint32_t a) {
    asm volatile(
        "ldmatrix.sync.aligned.m8n8.x4.trans.shared.b16 {%0,%1,%2,%3}, [%4];"
        : "=r"(r0), "=r"(r1), "=r"(r2), "=r"(r3) : "r"(a));
}
__device__ __forceinline__ void mma16816(float* c, const uint32_t* a,
                                         const uint32_t* b) {
    asm volatile(
        "mma.sync.aligned.m16n8k16.row.col.f32.f16.f16.f32 "
        "{%0,%1,%2,%3}, {%4,%5,%6,%7}, {%8,%9}, {%0,%1,%2,%3};"
        : "+f"(c[0]), "+f"(c[1]), "+f"(c[2]), "+f"(c[3])
        : "r"(a[0]), "r"(a[1]), "r"(a[2]), "r"(a[3]), "r"(b[0]), "r"(b[1]));
}

__device__ __forceinline__ size_t perm_fwd(size_t m) {
    int b = (int)(m / 3136), rem = (int)(m - (size_t)b * 3136);
    int oh = rem / 56, ow = rem - oh * 56;
    int hh = (oh >= 3) ? oh - 3 : oh + 53;
    int vv = (ow >= 3) ? ow - 3 : ow + 53;
    int w7 = hh / 7, v7 = vv / 7;
    int t  = (hh - w7 * 7) * 7 + (vv - v7 * 7);
    return ((size_t)(b * 64 + w7 * 8 + v7)) * 49 + t;
}
__device__ __forceinline__ size_t perm_inv(size_t r) {
    int w = (int)(r / 49), t = (int)(r - (size_t)w * 49);
    int b = w >> 6, wr = (w >> 3) & 7, wc = w & 7;
    int ih = t / 7, iw = t - ih * 7;
    int oh = wr * 7 + ih + 3; if (oh >= 56) oh -= 56;
    int ow = wc * 7 + iw + 3; if (ow >= 56) ow -= 56;
    return (size_t)b * 3136 + oh * 56 + ow;
}

// ======================= fp32 -> fp16 conversion ============================
__global__ void __launch_bounds__(256)
convert_h(const float* __restrict__ in, __half* __restrict__ out, int total4) {
    int t = blockIdx.x * 256 + threadIdx.x;
    if (t >= total4) return;
    float4 v = *(const float4*)(in + (size_t)t * 4);
    *(__half2*)(out + (size_t)t * 4)     = __floats2half2_rn(v.x, v.y);
    *(__half2*)(out + (size_t)t * 4 + 2) = __floats2half2_rn(v.z, v.w);
}

// ======================= bias+mask table build ==============================
__global__ void __launch_bounds__(256)
build_tbl(const float* __restrict__ table, __half* __restrict__ tbl) {
    int type = blockIdx.x >> 3;
    int head = blockIdx.x & 7;
    int wr = (type & 2) ? 7 : 0;
    int wc = (type & 1) ? 7 : 0;
    for (int idx = threadIdx.x; idx < 4096; idx += 256) {
        int i = idx >> 6, j = idx & 63;
        float v;
        if (j >= 49)      v = -1e4f;
        else if (i >= 49) v = 0.f;
        else {
            int ih = i / 7, iw = i - ih * 7;
            int jh = j / 7, jw = j - jh * 7;
            float bias = table[((ih - jh + 6) * 13 + (iw - jw + 6)) * 8 + head];
            int hh = wr * 7 + ih, vv = wc * 7 + iw;
            int hj = wr * 7 + jh, wj = wc * 7 + jw;
            int ri = ((hh < 49) ? 0 : (hh < 53 ? 1 : 2)) * 3 +
                     ((vv < 49) ? 0 : (vv < 53 ? 1 : 2));
            int rj = ((hj < 49) ? 0 : (hj < 53 ? 1 : 2)) * 3 +
                     ((wj < 49) ? 0 : (wj < 53 ? 1 : 2));
            v = bias + ((ri != rj) ? -100.f : 0.f);
        }
        tbl[(size_t)blockIdx.x * 4096 + idx] = __float2half_rn(v);
    }
}

// ======================= mma.sync GEMM (BK=64, 3-stage) =====================
// PERM=1 (QKV): A row-major; C head-major fp16, staged epilogue.
// PERM=2 (proj): A head-major acat; C row-major fp32 at perm_inv, staged.
#define MROW   144
#define MAT_ST (128 * MROW)
#define ST     (2 * MAT_ST)
#define NSTG   3
#define GEMM_SMEM (NSTG * ST)         // 110592 B

template <typename OT, int PERM>
__global__ void __launch_bounds__(256, 2)
gemm_mma(const __half* __restrict__ A, const __half* __restrict__ W,
         const float* __restrict__ bias, OT* __restrict__ C, int N) {
    extern __shared__ __half smbuf[];
    __shared__ int rowbase[128];

    const int tid  = threadIdx.x;
    const int wid  = tid >> 5;
    const int lane = tid & 31;
    const int wm   = wid & 3;
    const int wn   = wid >> 2;
    const size_t m0 = (size_t)blockIdx.y * 128;
    const int    n0 = blockIdx.x * 128;
    const uint32_t s0 = smem_u32(smbuf);

    float acc[2][8][4];
#pragma unroll
    for (int i = 0; i < 2; i++)
#pragma unroll
        for (int j = 0; j < 8; j++)
#pragma unroll
            for (int k = 0; k < 4; k++) acc[i][j][k] = 0.f;

    const __half* gA = A + m0 * KC;
    const __half* gB = W + (size_t)n0 * KC;

#define LOAD_SLAB(st, slab)                                                  \
    do {                                                                     \
        uint32_t ab_ = s0 + (st) * ST;                                       \
        uint32_t bb_ = ab_ + MAT_ST;                                         \
        int k0_ = (slab) * 64;                                               \
        _Pragma("unroll")                                                    \
        for (int i_ = 0; i_ < 4; i_++) {                                     \
            int seg_ = tid + i_ * 256;                                       \
            int r_ = seg_ >> 3, c_ = seg_ & 7;                               \
            uint32_t so_ = r_ * MROW + c_ * 16;                              \
            const __half* asrc_;                                             \
            if (PERM == 2) {                                                 \
                int m_ = (int)(m0) + r_;                                     \
                int win_ = m_ / 49, t_ = m_ - win_ * 49;                     \
                int head_ = (k0_ >> 5) + (c_ >> 2);                          \
                asrc_ = A + (((size_t)win_ * 8 + head_) * 49 + t_) * 32 +    \
                        (c_ & 3) * 8;                                        \
            } else {                                                         \
                asrc_ = gA + (size_t)r_ * KC + k0_ + c_ * 8;                 \
            }                                                                \
            cp16(ab_ + so_, asrc_);                                          \
            cp16(bb_ + so_, gB + (size_t)r_ * KC + k0_ + c_ * 8);            \
        }                                                                    \
    } while (0)

    const int NS = KC / 64;

    LOAD_SLAB(0, 0); CP_COMMIT();
    LOAD_SLAB(1, 1); CP_COMMIT();

    // precompute permuted row bases while pipeline warms up
    if (tid < 128) {
        if (PERM == 1) {
            size_t r = perm_fwd(m0 + tid);
            int win = (int)(r / 49), t = (int)(r - (size_t)win * 49);
            int mat   = n0 >> 8;
            int head0 = (n0 & 255) >> 5;
            rowbase[tid] = ((win * 3 + mat) * 8 + head0) * 1568 + t * 32;
        } else {
            rowbase[tid] = (int)(perm_inv(m0 + tid) * 256);
        }
    }

    const int aRow = wm * 32 + (lane & 15);
    const int aChk = lane >> 4;
    const int bRowBase = wn * 64 + (lane & 7) + ((lane >> 4) << 3);
    const int bChk = (lane >> 3) & 1;

    for (int f = 0; f < NS; f++) {
        CP_WAIT1();
        __syncthreads();

        const int st = (f < 3) ? f : 0;
        const uint32_t aBase = s0 + st * ST;
        const uint32_t bBase = aBase + MAT_ST;
#pragma unroll
        for (int kk = 0; kk < 4; kk++) {
            uint32_t af[2][4];
#pragma unroll
            for (int mt = 0; mt < 2; mt++) {
                uint32_t ad = aBase + (aRow + mt * 16) * MROW +
                              (kk * 2 + aChk) * 16;
                ldsm4(af[mt][0], af[mt][1], af[mt][2], af[mt][3], ad);
            }
            uint32_t bf[8][2];
#pragma unroll
            for (int pr = 0; pr < 4; pr++) {
                uint32_t bd = bBase + (bRowBase + pr * 16) * MROW +
                              (kk * 2 + bChk) * 16;
                uint32_t r0, r1, r2, r3;
                ldsm4(r0, r1, r2, r3, bd);
                bf[2 * pr][0] = r0; bf[2 * pr][1] = r1;
                bf[2 * pr + 1][0] = r2; bf[2 * pr + 1][1] = r3;
            }
#pragma unroll
            for (int mt = 0; mt < 2; mt++)
#pragma unroll
                for (int nt = 0; nt < 8; nt++)
                    mma16816(acc[mt][nt], af[mt], bf[nt]);
        }

        if (f + 2 < NS) {
            int st2 = f + 2 - 3 < 0 ? f + 2 : f - 1;
            LOAD_SLAB(st2, f + 2);
        }
        CP_COMMIT();
    }
#undef LOAD_SLAB

    CP_WAIT0();
    __syncthreads();

    const int g  = lane >> 2;
    const int t4 = lane & 3;

    if constexpr (PERM == 1) {
        // stage fp16 tile [128][136] (272B rows, 16B aligned)
        __half* S = smbuf;
#pragma unroll
        for (int nt = 0; nt < 8; nt++) {
            const int col = wn * 64 + nt * 8 + 2 * t4;
            float2 bb = *(const float2*)(bias + n0 + col);
#pragma unroll
            for (int mt = 0; mt < 2; mt++) {
                int row = wm * 32 + mt * 16 + g;
                *(__half2*)(S + row * 136 + col) =
                    __floats2half2_rn(acc[mt][nt][0] + bb.x,
                                      acc[mt][nt][1] + bb.y);
                *(__half2*)(S + (row + 8) * 136 + col) =
                    __floats2half2_rn(acc[mt][nt][2] + bb.x,
                                      acc[mt][nt][3] + bb.y);
            }
        }
        __syncthreads();
        // write out: 128 rows x 4 head-chunks x 4 x 16B = 2048 uint4
        __half* Cb = (__half*)C;
#pragma unroll
        for (int i = 0; i < 8; i++) {
            int idx = tid + i * 256;
            int r = idx >> 4, c = (idx >> 2) & 3, q = idx & 3;
            uint4 v = *(const uint4*)(S + r * 136 + c * 32 + q * 8);
            *(uint4*)(Cb + (size_t)rowbase[r] + c * 1568 + q * 8) = v;
        }
    } else {
        // stage fp32 tile [128][132] (528B rows, 16B aligned)
        float* S = (float*)smbuf;
#pragma unroll
        for (int nt = 0; nt < 8; nt++) {
            const int col = wn * 64 + nt * 8 + 2 * t4;
            float2 bb = *(const float2*)(bias + n0 + col);
#pragma unroll
            for (int mt = 0; mt < 2; mt++) {
                int row = wm * 32 + mt * 16 + g;
                *(float2*)(S + row * 132 + col) =
                    make_float2(acc[mt][nt][0] + bb.x, acc[mt][nt][1] + bb.y);
                *(float2*)(S + (row + 8) * 132 + col) =
                    make_float2(acc[mt][nt][2] + bb.x, acc[mt][nt][3] + bb.y);
            }
        }
        __syncthreads();
        // write out: 128 rows x 32 x 16B = 4096 uint4
        float* Cf = (float*)C;
#pragma unroll
        for (int i = 0; i < 16; i++) {
            int idx = tid + i * 256;
            int r = idx >> 5, q = idx & 31;
            uint4 v = *(const uint4*)(S + r * 132 + q * 4);
            *(uint4*)(Cf + (size_t)rowbase[r] + n0 + q * 4) = v;
        }
    }
}

// ======================= tensor-core attention ==============================
__global__ void __launch_bounds__(64)
attn_mma(const __half* __restrict__ qkv, const __half* __restrict__ tblg,
         __half* __restrict__ outp) {
    __shared__ __align__(16) __half Qs[64 * 40];
    __shared__ __align__(16) __half Ks[64 * 40];
    __shared__ __align__(16) __half Vs[64 * 40];
    __shared__ __align__(16) __half Ts[64 * 72];

    const int tid  = threadIdx.x;
    const int w    = tid >> 5;
    const int lane = tid & 31;
    const int head = blockIdx.x & 7;
    const int win  = blockIdx.x >> 3;
    const int wr   = (win >> 3) & 7;
    const int wc   = win & 7;

    {
        const int type = ((wr == 7) ? 2 : 0) | ((wc == 7) ? 1 : 0);
        const uint4* Tg = (const uint4*)(tblg + (size_t)(type * 8 + head) * 4096);
        for (int idx = tid; idx < 512; idx += 64) {
            int r = idx >> 3, c = idx & 7;
            *(uint4*)(Ts + r * 72 + c * 8) = Tg[idx];
        }
    }
    for (int idx = tid; idx < 180; idx += 64) {
        int mat = idx / 60, rem = idx - mat * 60;
        int r = 49 + (rem >> 2), q = rem & 3;
        __half* bp = (mat == 0) ? Qs : (mat == 1) ? Ks : Vs;
        *(uint4*)(bp + r * 40 + q * 8) = make_uint4(0, 0, 0, 0);
    }
    {
        const __half* srcQ = qkv + ((size_t)win * 24 + head) * 1568;
        const __half* srcK = srcQ + 8 * 1568;
        const __half* srcV = srcQ + 16 * 1568;
        for (int idx = tid; idx < 196; idx += 64) {
            int p = idx >> 2, q = idx & 3;
            int off = p * 32 + q * 8;
            *(uint4*)(Qs + p * 40 + q * 8) = *(const uint4*)(srcQ + off);
            *(uint4*)(Ks + p * 40 + q * 8) = *(const uint4*)(srcK + off);
            *(uint4*)(Vs + p * 40 + q * 8) = *(const uint4*)(srcV + off);
        }
    }
    __syncthreads();

    const uint32_t sQ = smem_u32(Qs), sK = smem_u32(Ks), sV = smem_u32(Vs);

    uint32_t aQ[2][2][4];
#pragma unroll
    for (int mt = 0; mt < 2; mt++)
#pragma unroll
        for (int kk = 0; kk < 2; kk++) {
            int row = w * 32 + mt * 16 + (lane & 15);
            uint32_t ad = sQ + row * 80 + (kk * 2 + (lane >> 4)) * 16;
            ldsm4(aQ[mt][kk][0], aQ[mt][kk][1], aQ[mt][kk][2], aQ[mt][kk][3], ad);
        }
    uint32_t bK[2][8][2];
#pragma unroll
    for (int kk = 0; kk < 2; kk++)
#pragma unroll
        for (int pr = 0; pr < 4; pr++) {
            int row = pr * 16 + (lane & 7) + ((lane >> 4) << 3);
            uint32_t ad = sK + row * 80 + (kk * 2 + ((lane >> 3) & 1)) * 16;
            uint32_t r0, r1, r2, r3;
            ldsm4(r0, r1, r2, r3, ad);
            bK[kk][2 * pr][0] = r0;     bK[kk][2 * pr][1] = r1;
            bK[kk][2 * pr + 1][0] = r2; bK[kk][2 * pr + 1][1] = r3;
        }
    float s[2][8][4];
#pragma unroll
    for (int mt = 0; mt < 2; mt++)
#pragma unroll
        for (int nt = 0; nt < 8; nt++) {
            s[mt][nt][0] = s[mt][nt][1] = s[mt][nt][2] = s[mt][nt][3] = 0.f;
            mma16816(s[mt][nt], aQ[mt][0], bK[0][nt]);
            mma16816(s[mt][nt], aQ[mt][1], bK[1][nt]);
        }

    const int g  = lane >> 2;
    const int t4 = lane & 3;
    const float scale = 0.17677669529663687f;

#pragma unroll
    for (int mt = 0; mt < 2; mt++)
#pragma unroll
        for (int h = 0; h < 2; h++) {
            const __half* trow = Ts + (w * 32 + mt * 16 + g + 8 * h) * 72;
#pragma unroll
            for (int nt = 0; nt < 8; nt++) {
                __half2 t2 = *(const __half2*)(trow + nt * 8 + 2 * t4);
                float2 tf = __half22float2(t2);
                s[mt][nt][2 * h]     = fmaf(s[mt][nt][2 * h],     scale, tf.x);
                s[mt][nt][2 * h + 1] = fmaf(s[mt][nt][2 * h + 1], scale, tf.y);
            }
        }

    float zinv[2][2];
#pragma unroll
    for (int mt = 0; mt < 2; mt++)
#pragma unroll
        for (int h = 0; h < 2; h++) {
            float m = -1e30f;
#pragma unroll
            for (int nt = 0; nt < 8; nt++) {
                m = fmaxf(m, s[mt][nt][2 * h]);
                m = fmaxf(m, s[mt][nt][2 * h + 1]);
            }
            m = fmaxf(m, __shfl_xor_sync(0xffffffffu, m, 1));
            m = fmaxf(m, __shfl_xor_sync(0xffffffffu, m, 2));
            float sum = 0.f;
#pragma unroll
            for (int nt = 0; nt < 8; nt++) {
                float e0 = __expf(s[mt][nt][2 * h] - m);
                float e1 = __expf(s[mt][nt][2 * h + 1] - m);
                s[mt][nt][2 * h] = e0;
                s[mt][nt][2 * h + 1] = e1;
                sum += e0 + e1;
            }
            sum += __shfl_xor_sync(0xffffffffu, sum, 1);
            sum += __shfl_xor_sync(0xffffffffu, sum, 2);
            zinv[mt][h] = 1.0f / sum;
        }

    uint32_t aP[2][4][4];
#pragma unroll
    for (int mt = 0; mt < 2; mt++)
#pragma unroll
        for (int kt = 0; kt < 4; kt++) {
            aP[mt][kt][0] = h2u(__floats2half2_rn(s[mt][2 * kt][0],
                                                  s[mt][2 * kt][1]));
            aP[mt][kt][1] = h2u(__floats2half2_rn(s[mt][2 * kt][2],
                                                  s[mt][2 * kt][3]));
            aP[mt][kt][2] = h2u(__floats2half2_rn(s[mt][2 * kt + 1][0],
                                                  s[mt][2 * kt + 1][1]));
            aP[mt][kt][3] = h2u(__floats2half2_rn(s[mt][2 * kt + 1][2],
                                                  s[mt][2 * kt + 1][3]));
        }

    uint32_t bV[4][4][2];
#pragma unroll
    for (int kt = 0; kt < 4; kt++)
#pragma unroll
        for (int nh = 0; nh < 2; nh++) {
            int row = kt * 16 + (lane & 7) + (((lane >> 3) & 1) << 3);
            uint32_t ad = sV + row * 80 + nh * 32 + ((lane >> 4) << 4);
            uint32_t r0, r1, r2, r3;
            ldsm4t(r0, r1, r2, r3, ad);
            bV[kt][2 * nh][0] = r0;     bV[kt][2 * nh][1] = r1;
            bV[kt][2 * nh + 1][0] = r2; bV[kt][2 * nh + 1][1] = r3;
        }

    float o[2][4][4];
#pragma unroll
    for (int mt = 0; mt < 2; mt++)
#pragma unroll
        for (int vn = 0; vn < 4; vn++) {
            o[mt][vn][0] = o[mt][vn][1] = o[mt][vn][2] = o[mt][vn][3] = 0.f;
#pragma unroll
            for (int kt = 0; kt < 4; kt++)
                mma16816(o[mt][vn], aP[mt][kt], bV[kt][vn]);
        }

    __half* obase = outp + ((size_t)win * 8 + head) * 1568;
#pragma unroll
    for (int mt = 0; mt < 2; mt++)
#pragma unroll
        for (int h = 0; h < 2; h++) {
            int i = w * 32 + mt * 16 + g + 8 * h;
            if (i >= 49) continue;
            float rz = zinv[mt][h];
            __half* dst = obase + i * 32;
#pragma unroll
            for (int vn = 0; vn < 4; vn++) {
                int col = vn * 8 + 2 * t4;
                *(__half2*)(dst + col) =
                    __floats2half2_rn(o[mt][vn][2 * h] * rz,
                                      o[mt][vn][2 * h + 1] * rz);
            }
        }
}

// ---------------------------------------------------------------------------
extern "C" void kernel_launch(void* const* d_in, const int* in_sizes, int n_in,
                              void* d_out, int out_size) {
    const float* x      = (const float*)d_in[0];
    const float* qkv_w  = (const float*)d_in[1];
    const float* qkv_b  = (const float*)d_in[2];
    const float* proj_w = (const float*)d_in[3];
    const float* proj_b = (const float*)d_in[4];
    const float* table  = (const float*)d_in[5];
    float* out = (float*)d_out;

    void *qkv_p, *x16_p, *acat_p, *wq_p, *wp_p, *tbl_p;
    cudaGetSymbolAddress(&qkv_p,  g_qkv);
    cudaGetSymbolAddress(&x16_p,  g_x16);
    cudaGetSymbolAddress(&acat_p, g_acat);
    cudaGetSymbolAddress(&wq_p,   g_wq);
    cudaGetSymbolAddress(&wp_p,   g_wp);
    cudaGetSymbolAddress(&tbl_p,  g_tbl);
    __half* qkv  = (__half*)qkv_p;
    __half* x16  = (__half*)x16_p;
    __half* acat = (__half*)acat_p;
    __half* wq   = (__half*)wq_p;
    __half* wp   = (__half*)wp_p;
    __half* tbl  = (__half*)tbl_p;

    static bool attr_done = false;
    if (!attr_done) {
        cudaFuncSetAttribute((const void*)gemm_mma<__half, 1>,
                             cudaFuncAttributeMaxDynamicSharedMemorySize,
                             GEMM_SMEM);
        cudaFuncSetAttribute((const void*)gemm_mma<float, 2>,
                             cudaFuncAttributeMaxDynamicSharedMemorySize,
                             GEMM_SMEM);
        attr_done = true;
    }

    convert_h<<<(M_ROWS * 64 + 255) / 256, 256>>>(x, x16, M_ROWS * 64);
    convert_h<<<(768 * 64 + 255) / 256, 256>>>(qkv_w, wq, 768 * 64);
    convert_h<<<(256 * 64 + 255) / 256, 256>>>(proj_w, wp, 256 * 64);
    build_tbl<<<32, 256>>>(table, tbl);

    dim3 gq(768 / 128, M_ROWS / 128);
    gemm_mma<__half, 1><<<gq, 256, GEMM_SMEM>>>(x16, wq, qkv_b, qkv, 768);

    attn_mma<<<2048 * 8, 64>>>(qkv, tbl, acat);

    dim3 gp(256 / 128, M_ROWS / 128);
    gemm_mma<float, 2><<<gp, 256, GEMM_SMEM>>>(acat, wp, proj_b, out, 256);
}

// round 16
// speedup vs baseline: 1.2645x; 1.0494x over previous
#include <cuda_runtime.h>
#include <cuda_fp16.h>
#include <cstdint>

// ---------------------------------------------------------------------------
// Swin shifted-window attention, B=32 H=W=56 C=256, 7x7 win, shift 3, 8 heads.
// Plain fp16 GEMMs (K=256), fp32 accumulate. Head-major intermediates:
//   g_qkv : [win][mat(q,k,v)][head][49][32]
//   g_acat: [win][head][49][32]
// Roll+window permutation folded into GEMM epilogues (smem-staged stores).
// Attention: 128 threads/block, 4 warps each owning one m16 row tile.
// ---------------------------------------------------------------------------

#define M_ROWS 100352           // 32*56*56 == 2048*49
#define KC     256

__device__ __half g_qkv[2048ULL * 3 * 8 * 49 * 32];
__device__ __half g_x16[100352ULL * 256];
__device__ __half g_acat[2048ULL * 8 * 49 * 32];
__device__ __half g_wq[768ULL * 256];
__device__ __half g_wp[256ULL * 256];
__device__ __half g_tbl[4 * 8 * 64 * 64];

// ======================= helpers ============================================
__device__ __forceinline__ uint32_t smem_u32(const void* p) {
    uint32_t a;
    asm("{ .reg .u64 t; cvta.to.shared.u64 t, %1; cvt.u32.u64 %0, t; }"
        : "=r"(a) : "l"(p));
    return a;
}
__device__ __forceinline__ uint32_t h2u(__half2 h) {
    union { __half2 h; uint32_t u; } c;
    c.h = h;
    return c.u;
}
__device__ __forceinline__ void cp16(uint32_t s, const void* g) {
    asm volatile("cp.async.cg.shared.global [%0], [%1], 16;"
                 :: "r"(s), "l"(g) : "memory");
}
#define CP_COMMIT() asm volatile("cp.async.commit_group;" ::: "memory")
#define CP_WAIT1()  asm volatile("cp.async.wait_group 1;" ::: "memory")
#define CP_WAIT0()  asm volatile("cp.async.wait_group 0;" ::: "memory")

__device__ __forceinline__ void ldsm4(uint32_t& r0, uint32_t& r1,
                                      uint32_t& r2, uint32_t& r3, uint32_t a) {
    asm volatile("ldmatrix.sync.aligned.m8n8.x4.shared.b16 {%0,%1,%2,%3}, [%4];"
                 : "=r"(r0), "=r"(r1), "=r"(r2), "=r"(r3) : "r"(a));
}
__device__ __forceinline__ void ldsm4t(uint32_t& r0, uint32_t& r1,
                                       uint32_t& r2, uint32_t& r3, uint32_t a) {
    asm volatile(
        "ldmatrix.sync.aligned.m8n8.x4.trans.shared.b16 {%0,%1,%2,%3}, [%4];"
        : "=r"(r0), "=r"(r1), "=r"(r2), "=r"(r3) : "r"(a));
}
__device__ __forceinline__ void mma16816(float* c, const uint32_t* a,
                                         const uint32_t* b) {
    asm volatile(
        "mma.sync.aligned.m16n8k16.row.col.f32.f16.f16.f32 "
        "{%0,%1,%2,%3}, {%4,%5,%6,%7}, {%8,%9}, {%0,%1,%2,%3};"
        : "+f"(c[0]), "+f"(c[1]), "+f"(c[2]), "+f"(c[3])
        : "r"(a[0]), "r"(a[1]), "r"(a[2]), "r"(a[3]), "r"(b[0]), "r"(b[1]));
}

__device__ __forceinline__ size_t perm_fwd(size_t m) {
    int b = (int)(m / 3136), rem = (int)(m - (size_t)b * 3136);
    int oh = rem / 56, ow = rem - oh * 56;
    int hh = (oh >= 3) ? oh - 3 : oh + 53;
    int vv = (ow >= 3) ? ow - 3 : ow + 53;
    int w7 = hh / 7, v7 = vv / 7;
    int t  = (hh - w7 * 7) * 7 + (vv - v7 * 7);
    return ((size_t)(b * 64 + w7 * 8 + v7)) * 49 + t;
}
__device__ __forceinline__ size_t perm_inv(size_t r) {
    int w = (int)(r / 49), t = (int)(r - (size_t)w * 49);
    int b = w >> 6, wr = (w >> 3) & 7, wc = w & 7;
    int ih = t / 7, iw = t - ih * 7;
    int oh = wr * 7 + ih + 3; if (oh >= 56) oh -= 56;
    int ow = wc * 7 + iw + 3; if (ow >= 56) ow -= 56;
    return (size_t)b * 3136 + oh * 56 + ow;
}

// ======================= fp32 -> fp16 conversion ============================
__global__ void __launch_bounds__(256)
convert_h(const float* __restrict__ in, __half* __restrict__ out, int total4) {
    int t = blockIdx.x * 256 + threadIdx.x;
    if (t >= total4) return;
    float4 v = *(const float4*)(in + (size_t)t * 4);
    *(__half2*)(out + (size_t)t * 4)     = __floats2half2_rn(v.x, v.y);
    *(__half2*)(out + (size_t)t * 4 + 2) = __floats2half2_rn(v.z, v.w);
}

// ======================= bias+mask table build ==============================
__global__ void __launch_bounds__(256)
build_tbl(const float* __restrict__ table, __half* __restrict__ tbl) {
    int type = blockIdx.x >> 3;
    int head = blockIdx.x & 7;
    int wr = (type & 2) ? 7 : 0;
    int wc = (type & 1) ? 7 : 0;
    for (int idx = threadIdx.x; idx < 4096; idx += 256) {
        int i = idx >> 6, j = idx & 63;
        float v;
        if (j >= 49)      v = -1e4f;
        else if (i >= 49) v = 0.f;
        else {
            int ih = i / 7, iw = i - ih * 7;
            int jh = j / 7, jw = j - jh * 7;
            float bias = table[((ih - jh + 6) * 13 + (iw - jw + 6)) * 8 + head];
            int hh = wr * 7 + ih, vv = wc * 7 + iw;
            int hj = wr * 7 + jh, wj = wc * 7 + jw;
            int ri = ((hh < 49) ? 0 : (hh < 53 ? 1 : 2)) * 3 +
                     ((vv < 49) ? 0 : (vv < 53 ? 1 : 2));
            int rj = ((hj < 49) ? 0 : (hj < 53 ? 1 : 2)) * 3 +
                     ((wj < 49) ? 0 : (wj < 53 ? 1 : 2));
            v = bias + ((ri != rj) ? -100.f : 0.f);
        }
        tbl[(size_t)blockIdx.x * 4096 + idx] = __float2half_rn(v);
    }
}

// ======================= mma.sync GEMM (BK=64, 3-stage) =====================
#define MROW   144
#define MAT_ST (128 * MROW)
#define ST     (2 * MAT_ST)
#define NSTG   3
#define GEMM_SMEM (NSTG * ST)         // 110592 B

template <typename OT, int PERM>
__global__ void __launch_bounds__(256, 2)
gemm_mma(const __half* __restrict__ A, const __half* __restrict__ W,
         const float* __restrict__ bias, OT* __restrict__ C, int N) {
    extern __shared__ __half smbuf[];
    __shared__ int rowbase[128];

    const int tid  = threadIdx.x;
    const int wid  = tid >> 5;
    const int lane = tid & 31;
    const int wm   = wid & 3;
    const int wn   = wid >> 2;
    const size_t m0 = (size_t)blockIdx.y * 128;
    const int    n0 = blockIdx.x * 128;
    const uint32_t s0 = smem_u32(smbuf);

    float acc[2][8][4];
#pragma unroll
    for (int i = 0; i < 2; i++)
#pragma unroll
        for (int j = 0; j < 8; j++)
#pragma unroll
            for (int k = 0; k < 4; k++) acc[i][j][k] = 0.f;

    const __half* gA = A + m0 * KC;
    const __half* gB = W + (size_t)n0 * KC;

#define LOAD_SLAB(st, slab)                                                  \
    do {                                                                     \
        uint32_t ab_ = s0 + (st) * ST;                                       \
        uint32_t bb_ = ab_ + MAT_ST;                                         \
        int k0_ = (slab) * 64;                                               \
        _Pragma("unroll")                                                    \
        for (int i_ = 0; i_ < 4; i_++) {                                     \
            int seg_ = tid + i_ * 256;                                       \
            int r_ = seg_ >> 3, c_ = seg_ & 7;                               \
            uint32_t so_ = r_ * MROW + c_ * 16;                              \
            const __half* asrc_;                                             \
            if (PERM == 2) {                                                 \
                int m_ = (int)(m0) + r_;                                     \
                int win_ = m_ / 49, t_ = m_ - win_ * 49;                     \
                int head_ = (k0_ >> 5) + (c_ >> 2);                          \
                asrc_ = A + (((size_t)win_ * 8 + head_) * 49 + t_) * 32 +    \
                        (c_ & 3) * 8;                                        \
            } else {                                                         \
                asrc_ = gA + (size_t)r_ * KC + k0_ + c_ * 8;                 \
            }                                                                \
            cp16(ab_ + so_, asrc_);                                          \
            cp16(bb_ + so_, gB + (size_t)r_ * KC + k0_ + c_ * 8);            \
        }                                                                    \
    } while (0)

    const int NS = KC / 64;

    LOAD_SLAB(0, 0); CP_COMMIT();
    LOAD_SLAB(1, 1); CP_COMMIT();

    if (tid < 128) {
        if (PERM == 1) {
            size_t r = perm_fwd(m0 + tid);
            int win = (int)(r / 49), t = (int)(r - (size_t)win * 49);
            int mat   = n0 >> 8;
            int head0 = (n0 & 255) >> 5;
            rowbase[tid] = ((win * 3 + mat) * 8 + head0) * 1568 + t * 32;
        } else {
            rowbase[tid] = (int)(perm_inv(m0 + tid) * 256);
        }
    }

    const int aRow = wm * 32 + (lane & 15);
    const int aChk = lane >> 4;
    const int bRowBase = wn * 64 + (lane & 7) + ((lane >> 4) << 3);
    const int bChk = (lane >> 3) & 1;

    for (int f = 0; f < NS; f++) {
        CP_WAIT1();
        __syncthreads();

        const int st = (f < 3) ? f : 0;
        const uint32_t aBase = s0 + st * ST;
        const uint32_t bBase = aBase + MAT_ST;
#pragma unroll
        for (int kk = 0; kk < 4; kk++) {
            uint32_t af[2][4];
#pragma unroll
            for (int mt = 0; mt < 2; mt++) {
                uint32_t ad = aBase + (aRow + mt * 16) * MROW +
                              (kk * 2 + aChk) * 16;
                ldsm4(af[mt][0], af[mt][1], af[mt][2], af[mt][3], ad);
            }
            uint32_t bf[8][2];
#pragma unroll
            for (int pr = 0; pr < 4; pr++) {
                uint32_t bd = bBase + (bRowBase + pr * 16) * MROW +
                              (kk * 2 + bChk) * 16;
                uint32_t r0, r1, r2, r3;
                ldsm4(r0, r1, r2, r3, bd);
                bf[2 * pr][0] = r0; bf[2 * pr][1] = r1;
                bf[2 * pr + 1][0] = r2; bf[2 * pr + 1][1] = r3;
            }
#pragma unroll
            for (int mt = 0; mt < 2; mt++)
#pragma unroll
                for (int nt = 0; nt < 8; nt++)
                    mma16816(acc[mt][nt], af[mt], bf[nt]);
        }

        if (f + 2 < NS) {
            int st2 = f + 2 - 3 < 0 ? f + 2 : f - 1;
            LOAD_SLAB(st2, f + 2);
        }
        CP_COMMIT();
    }
#undef LOAD_SLAB

    CP_WAIT0();
    __syncthreads();

    const int g  = lane >> 2;
    const int t4 = lane & 3;

    if constexpr (PERM == 1) {
        __half* S = smbuf;
#pragma unroll
        for (int nt = 0; nt < 8; nt++) {
            const int col = wn * 64 + nt * 8 + 2 * t4;
            float2 bb = *(const float2*)(bias + n0 + col);
#pragma unroll
            for (int mt = 0; mt < 2; mt++) {
                int row = wm * 32 + mt * 16 + g;
                *(__half2*)(S + row * 136 + col) =
                    __floats2half2_rn(acc[mt][nt][0] + bb.x,
                                      acc[mt][nt][1] + bb.y);
                *(__half2*)(S + (row + 8) * 136 + col) =
                    __floats2half2_rn(acc[mt][nt][2] + bb.x,
                                      acc[mt][nt][3] + bb.y);
            }
        }
        __syncthreads();
        __half* Cb = (__half*)C;
#pragma unroll
        for (int i = 0; i < 8; i++) {
            int idx = tid + i * 256;
            int r = idx >> 4, c = (idx >> 2) & 3, q = idx & 3;
            uint4 v = *(const uint4*)(S + r * 136 + c * 32 + q * 8);
            *(uint4*)(Cb + (size_t)rowbase[r] + c * 1568 + q * 8) = v;
        }
    } else {
        float* S = (float*)smbuf;
#pragma unroll
        for (int nt = 0; nt < 8; nt++) {
            const int col = wn * 64 + nt * 8 + 2 * t4;
            float2 bb = *(const float2*)(bias + n0 + col);
#pragma unroll
            for (int mt = 0; mt < 2; mt++) {
                int row = wm * 32 + mt * 16 + g;
                *(float2*)(S + row * 132 + col) =
                    make_float2(acc[mt][nt][0] + bb.x, acc[mt][nt][1] + bb.y);
                *(float2*)(S + (row + 8) * 132 + col) =
                    make_float2(acc[mt][nt][2] + bb.x, acc[mt][nt][3] + bb.y);
            }
        }
        __syncthreads();
        float* Cf = (float*)C;
#pragma unroll
        for (int i = 0; i < 16; i++) {
            int idx = tid + i * 256;
            int r = idx >> 5, q = idx & 31;
            uint4 v = *(const uint4*)(S + r * 132 + q * 4);
            *(uint4*)(Cf + (size_t)rowbase[r] + n0 + q * 4) = v;
        }
    }
}

// ======================= tensor-core attention ==============================
// Block = (window, head), 128 threads (4 warps), warp w owns rows w*16..w*16+15.
__global__ void __launch_bounds__(128)
attn_mma(const __half* __restrict__ qkv, const __half* __restrict__ tblg,
         __half* __restrict__ outp) {
    __shared__ __align__(16) __half Qs[64 * 40];
    __shared__ __align__(16) __half Ks[64 * 40];
    __shared__ __align__(16) __half Vs[64 * 40];
    __shared__ __align__(16) __half Ts[64 * 72];

    const int tid  = threadIdx.x;
    const int w    = tid >> 5;
    const int lane = tid & 31;
    const int head = blockIdx.x & 7;
    const int win  = blockIdx.x >> 3;
    const int wr   = (win >> 3) & 7;
    const int wc   = win & 7;

    {
        const int type = ((wr == 7) ? 2 : 0) | ((wc == 7) ? 1 : 0);
        const uint4* Tg = (const uint4*)(tblg + (size_t)(type * 8 + head) * 4096);
        for (int idx = tid; idx < 512; idx += 128) {
            int r = idx >> 3, c = idx & 7;
            *(uint4*)(Ts + r * 72 + c * 8) = Tg[idx];
        }
    }
    for (int idx = tid; idx < 180; idx += 128) {
        int mat = idx / 60, rem = idx - mat * 60;
        int r = 49 + (rem >> 2), q = rem & 3;
        __half* bp = (mat == 0) ? Qs : (mat == 1) ? Ks : Vs;
        *(uint4*)(bp + r * 40 + q * 8) = make_uint4(0, 0, 0, 0);
    }
    {
        const __half* srcQ = qkv + ((size_t)win * 24 + head) * 1568;
        const __half* srcK = srcQ + 8 * 1568;
        const __half* srcV = srcQ + 16 * 1568;
        for (int idx = tid; idx < 196; idx += 128) {
            int p = idx >> 2, q = idx & 3;
            int off = p * 32 + q * 8;
            *(uint4*)(Qs + p * 40 + q * 8) = *(const uint4*)(srcQ + off);
            *(uint4*)(Ks + p * 40 + q * 8) = *(const uint4*)(srcK + off);
            *(uint4*)(Vs + p * 40 + q * 8) = *(const uint4*)(srcV + off);
        }
    }
    __syncthreads();

    const uint32_t sQ = smem_u32(Qs), sK = smem_u32(Ks), sV = smem_u32(Vs);

    // ---- S = Q K^T (one m16 tile per warp) ----
    uint32_t aQ[2][4];
#pragma unroll
    for (int kk = 0; kk < 2; kk++) {
        int row = w * 16 + (lane & 15);
        uint32_t ad = sQ + row * 80 + (kk * 2 + (lane >> 4)) * 16;
        ldsm4(aQ[kk][0], aQ[kk][1], aQ[kk][2], aQ[kk][3], ad);
    }
    uint32_t bK[2][8][2];
#pragma unroll
    for (int kk = 0; kk < 2; kk++)
#pragma unroll
        for (int pr = 0; pr < 4; pr++) {
            int row = pr * 16 + (lane & 7) + ((lane >> 4) << 3);
            uint32_t ad = sK + row * 80 + (kk * 2 + ((lane >> 3) & 1)) * 16;
            uint32_t r0, r1, r2, r3;
            ldsm4(r0, r1, r2, r3, ad);
            bK[kk][2 * pr][0] = r0;     bK[kk][2 * pr][1] = r1;
            bK[kk][2 * pr + 1][0] = r2; bK[kk][2 * pr + 1][1] = r3;
        }
    float s[8][4];
#pragma unroll
    for (int nt = 0; nt < 8; nt++) {
        s[nt][0] = s[nt][1] = s[nt][2] = s[nt][3] = 0.f;
        mma16816(s[nt], aQ[0], bK[0][nt]);
        mma16816(s[nt], aQ[1], bK[1][nt]);
    }

    const int g  = lane >> 2;
    const int t4 = lane & 3;
    const float scale = 0.17677669529663687f;

    // ---- logits ----
#pragma unroll
    for (int h = 0; h < 2; h++) {
        const __half* trow = Ts + (w * 16 + g + 8 * h) * 72;
#pragma unroll
        for (int nt = 0; nt < 8; nt++) {
            __half2 t2 = *(const __half2*)(trow + nt * 8 + 2 * t4);
            float2 tf = __half22float2(t2);
            s[nt][2 * h]     = fmaf(s[nt][2 * h],     scale, tf.x);
            s[nt][2 * h + 1] = fmaf(s[nt][2 * h + 1], scale, tf.y);
        }
    }

    // ---- softmax ----
    float zinv[2];
#pragma unroll
    for (int h = 0; h < 2; h++) {
        float m = -1e30f;
#pragma unroll
        for (int nt = 0; nt < 8; nt++) {
            m = fmaxf(m, s[nt][2 * h]);
            m = fmaxf(m, s[nt][2 * h + 1]);
        }
        m = fmaxf(m, __shfl_xor_sync(0xffffffffu, m, 1));
        m = fmaxf(m, __shfl_xor_sync(0xffffffffu, m, 2));
        float sum = 0.f;
#pragma unroll
        for (int nt = 0; nt < 8; nt++) {
            float e0 = __expf(s[nt][2 * h] - m);
            float e1 = __expf(s[nt][2 * h + 1] - m);
            s[nt][2 * h] = e0;
            s[nt][2 * h + 1] = e1;
            sum += e0 + e1;
        }
        sum += __shfl_xor_sync(0xffffffffu, sum, 1);
        sum += __shfl_xor_sync(0xffffffffu, sum, 2);
        zinv[h] = 1.0f / sum;
    }

    // ---- P fragments ----
    uint32_t aP[4][4];
#pragma unroll
    for (int kt = 0; kt < 4; kt++) {
        aP[kt][0] = h2u(__floats2half2_rn(s[2 * kt][0], s[2 * kt][1]));
        aP[kt][1] = h2u(__floats2half2_rn(s[2 * kt][2], s[2 * kt][3]));
        aP[kt][2] = h2u(__floats2half2_rn(s[2 * kt + 1][0], s[2 * kt + 1][1]));
        aP[kt][3] = h2u(__floats2half2_rn(s[2 * kt + 1][2], s[2 * kt + 1][3]));
    }

    // ---- V fragments ----
    uint32_t bV[4][4][2];
#pragma unroll
    for (int kt = 0; kt < 4; kt++)
#pragma unroll
        for (int nh = 0; nh < 2; nh++) {
            int row = kt * 16 + (lane & 7) + (((lane >> 3) & 1) << 3);
            uint32_t ad = sV + row * 80 + nh * 32 + ((lane >> 4) << 4);
            uint32_t r0, r1, r2, r3;
            ldsm4t(r0, r1, r2, r3, ad);
            bV[kt][2 * nh][0] = r0;     bV[kt][2 * nh][1] = r1;
            bV[kt][2 * nh + 1][0] = r2; bV[kt][2 * nh + 1][1] = r3;
        }

    // ---- O = P V ----
    float o[4][4];
#pragma unroll
    for (int vn = 0; vn < 4; vn++) {
        o[vn][0] = o[vn][1] = o[vn][2] = o[vn][3] = 0.f;
#pragma unroll
        for (int kt = 0; kt < 4; kt++)
            mma16816(o[vn], aP[kt], bV[kt][vn]);
    }

    // ---- store ----
    __half* obase = outp + ((size_t)win * 8 + head) * 1568;
#pragma unroll
    for (int h = 0; h < 2; h++) {
        int i = w * 16 + g + 8 * h;
        if (i >= 49) continue;
        float rz = zinv[h];
        __half* dst = obase + i * 32;
#pragma unroll
        for (int vn = 0; vn < 4; vn++) {
            int col = vn * 8 + 2 * t4;
            *(__half2*)(dst + col) =
                __floats2half2_rn(o[vn][2 * h] * rz, o[vn][2 * h + 1] * rz);
        }
    }
}

// ---------------------------------------------------------------------------
extern "C" void kernel_launch(void* const* d_in, const int* in_sizes, int n_in,
                              void* d_out, int out_size) {
    const float* x      = (const float*)d_in[0];
    const float* qkv_w  = (const float*)d_in[1];
    const float* qkv_b  = (const float*)d_in[2];
    const float* proj_w = (const float*)d_in[3];
    const float* proj_b = (const float*)d_in[4];
    const float* table  = (const float*)d_in[5];
    float* out = (float*)d_out;

    void *qkv_p, *x16_p, *acat_p, *wq_p, *wp_p, *tbl_p;
    cudaGetSymbolAddress(&qkv_p,  g_qkv);
    cudaGetSymbolAddress(&x16_p,  g_x16);
    cudaGetSymbolAddress(&acat_p, g_acat);
    cudaGetSymbolAddress(&wq_p,   g_wq);
    cudaGetSymbolAddress(&wp_p,   g_wp);
    cudaGetSymbolAddress(&tbl_p,  g_tbl);
    __half* qkv  = (__half*)qkv_p;
    __half* x16  = (__half*)x16_p;
    __half* acat = (__half*)acat_p;
    __half* wq   = (__half*)wq_p;
    __half* wp   = (__half*)wp_p;
    __half* tbl  = (__half*)tbl_p;

    static bool attr_done = false;
    if (!attr_done) {
        cudaFuncSetAttribute((const void*)gemm_mma<__half, 1>,
                             cudaFuncAttributeMaxDynamicSharedMemorySize,
                             GEMM_SMEM);
        cudaFuncSetAttribute((const void*)gemm_mma<float, 2>,
                             cudaFuncAttributeMaxDynamicSharedMemorySize,
                             GEMM_SMEM);
        attr_done = true;
    }

    convert_h<<<(M_ROWS * 64 + 255) / 256, 256>>>(x, x16, M_ROWS * 64);
    convert_h<<<(768 * 64 + 255) / 256, 256>>>(qkv_w, wq, 768 * 64);
    convert_h<<<(256 * 64 + 255) / 256, 256>>>(proj_w, wp, 256 * 64);
    build_tbl<<<32, 256>>>(table, tbl);

    dim3 gq(768 / 128, M_ROWS / 128);
    gemm_mma<__half, 1><<<gq, 256, GEMM_SMEM>>>(x16, wq, qkv_b, qkv, 768);

    attn_mma<<<2048 * 8, 128>>>(qkv, tbl, acat);

    dim3 gp(256 / 128, M_ROWS / 128);
    gemm_mma<float, 2><<<gp, 256, GEMM_SMEM>>>(acat, wp, proj_b, out, 256);
}

// round 17
// speedup vs baseline: 1.2736x; 1.0072x over previous
#include <cuda_runtime.h>
#include <cuda_fp16.h>
#include <cstdint>

// ---------------------------------------------------------------------------
// Swin shifted-window attention, B=32 H=W=56 C=256, 7x7 win, shift 3, 8 heads.
// fp16 GEMMs (K=256), fp32 accumulate. Head-major intermediates:
//   g_qkv : [win][mat(q,k,v)][head][49][32]
//   g_acat: [win][head][49][32]
// Roll+window perm folded into GEMM epilogues (smem-staged stores).
// Attention: block = (chunk of 8 windows, type, head); bias table staged once,
// QKV double-buffered via cp.async across the 8 windows.
// ---------------------------------------------------------------------------

#define M_ROWS 100352           // 32*56*56 == 2048*49
#define KC     256

__device__ __half g_qkv[2048ULL * 3 * 8 * 49 * 32];
__device__ __half g_x16[100352ULL * 256];
__device__ __half g_acat[2048ULL * 8 * 49 * 32];
__device__ __half g_wq[768ULL * 256];
__device__ __half g_wp[256ULL * 256];
__device__ __half g_tbl[4 * 8 * 64 * 64];

// ======================= helpers ============================================
__device__ __forceinline__ uint32_t smem_u32(const void* p) {
    uint32_t a;
    asm("{ .reg .u64 t; cvta.to.shared.u64 t, %1; cvt.u32.u64 %0, t; }"
        : "=r"(a) : "l"(p));
    return a;
}
__device__ __forceinline__ uint32_t h2u(__half2 h) {
    union { __half2 h; uint32_t u; } c;
    c.h = h;
    return c.u;
}
__device__ __forceinline__ void cp16(uint32_t s, const void* g) {
    asm volatile("cp.async.cg.shared.global [%0], [%1], 16;"
                 :: "r"(s), "l"(g) : "memory");
}
#define CP_COMMIT() asm volatile("cp.async.commit_group;" ::: "memory")
#define CP_WAIT1()  asm volatile("cp.async.wait_group 1;" ::: "memory")
#define CP_WAIT0()  asm volatile("cp.async.wait_group 0;" ::: "memory")

__device__ __forceinline__ void ldsm4(uint32_t& r0, uint32_t& r1,
                                      uint32_t& r2, uint32_t& r3, uint32_t a) {
    asm volatile("ldmatrix.sync.aligned.m8n8.x4.shared.b16 {%0,%1,%2,%3}, [%4];"
                 : "=r"(r0), "=r"(r1), "=r"(r2), "=r"(r3) : "r"(a));
}
__device__ __forceinline__ void ldsm4t(uint32_t& r0, uint32_t& r1,
                                       uint32_t& r2, uint32_t& r3, uint32_t a) {
    asm volatile(
        "ldmatrix.sync.aligned.m8n8.x4.trans.shared.b16 {%0,%1,%2,%3}, [%4];"
        : "=r"(r0), "=r"(r1), "=r"(r2), "=r"(r3) : "r"(a));
}
__device__ __forceinline__ void mma16816(float* c, const uint32_t* a,
                                         const uint32_t* b) {
    asm volatile(
        "mma.sync.aligned.m16n8k16.row.col.f32.f16.f16.f32 "
        "{%0,%1,%2,%3}, {%4,%5,%6,%7}, {%8,%9}, {%0,%1,%2,%3};"
        : "+f"(c[0]), "+f"(c[1]), "+f"(c[2]), "+f"(c[3])
        : "r"(a[0]), "r"(a[1]), "r"(a[2]), "r"(a[3]), "r"(b[0]), "r"(b[1]));
}

__device__ __forceinline__ size_t perm_fwd(size_t m) {
    int b = (int)(m / 3136), rem = (int)(m - (size_t)b * 3136);
    int oh = rem / 56, ow = rem - oh * 56;
    int hh = (oh >= 3) ? oh - 3 : oh + 53;
    int vv = (ow >= 3) ? ow - 3 : ow + 53;
    int w7 = hh / 7, v7 = vv / 7;
    int t  = (hh - w7 * 7) * 7 + (vv - v7 * 7);
    return ((size_t)(b * 64 + w7 * 8 + v7)) * 49 + t;
}
__device__ __forceinline__ size_t perm_inv(size_t r) {
    int w = (int)(r / 49), t = (int)(r - (size_t)w * 49);
    int b = w >> 6, wr = (w >> 3) & 7, wc = w & 7;
    int ih = t / 7, iw = t - ih * 7;
    int oh = wr * 7 + ih + 3; if (oh >= 56) oh -= 56;
    int ow = wc * 7 + iw + 3; if (ow >= 56) ow -= 56;
    return (size_t)b * 3136 + oh * 56 + ow;
}

// ======================= fp32 -> fp16 conversion ============================
__global__ void __launch_bounds__(256)
convert_h(const float* __restrict__ in, __half* __restrict__ out, int total4) {
    int t = blockIdx.x * 256 + threadIdx.x;
    if (t >= total4) return;
    float4 v = *(const float4*)(in + (size_t)t * 4);
    *(__half2*)(out + (size_t)t * 4)     = __floats2half2_rn(v.x, v.y);
    *(__half2*)(out + (size_t)t * 4 + 2) = __floats2half2_rn(v.z, v.w);
}

// ======================= bias+mask table build ==============================
__global__ void __launch_bounds__(256)
build_tbl(const float* __restrict__ table, __half* __restrict__ tbl) {
    int type = blockIdx.x >> 3;
    int head = blockIdx.x & 7;
    int wr = (type & 2) ? 7 : 0;
    int wc = (type & 1) ? 7 : 0;
    for (int idx = threadIdx.x; idx < 4096; idx += 256) {
        int i = idx >> 6, j = idx & 63;
        float v;
        if (j >= 49)      v = -1e4f;
        else if (i >= 49) v = 0.f;
        else {
            int ih = i / 7, iw = i - ih * 7;
            int jh = j / 7, jw = j - jh * 7;
            float bias = table[((ih - jh + 6) * 13 + (iw - jw + 6)) * 8 + head];
            int hh = wr * 7 + ih, vv = wc * 7 + iw;
            int hj = wr * 7 + jh, wj = wc * 7 + jw;
            int ri = ((hh < 49) ? 0 : (hh < 53 ? 1 : 2)) * 3 +
                     ((vv < 49) ? 0 : (vv < 53 ? 1 : 2));
            int rj = ((hj < 49) ? 0 : (hj < 53 ? 1 : 2)) * 3 +
                     ((wj < 49) ? 0 : (wj < 53 ? 1 : 2));
            v = bias + ((ri != rj) ? -100.f : 0.f);
        }
        tbl[(size_t)blockIdx.x * 4096 + idx] = __float2half_rn(v);
    }
}

// ======================= mma.sync GEMM (BK=64, 3-stage) =====================
#define MROW   144
#define MAT_ST (128 * MROW)
#define ST     (2 * MAT_ST)
#define NSTG   3
#define GEMM_SMEM (NSTG * ST)         // 110592 B

template <typename OT, int PERM>
__global__ void __launch_bounds__(256, 2)
gemm_mma(const __half* __restrict__ A, const __half* __restrict__ W,
         const float* __restrict__ bias, OT* __restrict__ C, int N) {
    extern __shared__ __half smbuf[];
    __shared__ int rowbase[128];

    const int tid  = threadIdx.x;
    const int wid  = tid >> 5;
    const int lane = tid & 31;
    const int wm   = wid & 3;
    const int wn   = wid >> 2;
    const size_t m0 = (size_t)blockIdx.y * 128;
    const int    n0 = blockIdx.x * 128;
    const uint32_t s0 = smem_u32(smbuf);

    float acc[2][8][4];
#pragma unroll
    for (int i = 0; i < 2; i++)
#pragma unroll
        for (int j = 0; j < 8; j++)
#pragma unroll
            for (int k = 0; k < 4; k++) acc[i][j][k] = 0.f;

    const __half* gA = A + m0 * KC;
    const __half* gB = W + (size_t)n0 * KC;

#define LOAD_SLAB(st, slab)                                                  \
    do {                                                                     \
        uint32_t ab_ = s0 + (st) * ST;                                       \
        uint32_t bb_ = ab_ + MAT_ST;                                         \
        int k0_ = (slab) * 64;                                               \
        _Pragma("unroll")                                                    \
        for (int i_ = 0; i_ < 4; i_++) {                                     \
            int seg_ = tid + i_ * 256;                                       \
            int r_ = seg_ >> 3, c_ = seg_ & 7;                               \
            uint32_t so_ = r_ * MROW + c_ * 16;                              \
            const __half* asrc_;                                             \
            if (PERM == 2) {                                                 \
                int m_ = (int)(m0) + r_;                                     \
                int win_ = m_ / 49, t_ = m_ - win_ * 49;                     \
                int head_ = (k0_ >> 5) + (c_ >> 2);                          \
                asrc_ = A + (((size_t)win_ * 8 + head_) * 49 + t_) * 32 +    \
                        (c_ & 3) * 8;                                        \
            } else {                                                         \
                asrc_ = gA + (size_t)r_ * KC + k0_ + c_ * 8;                 \
            }                                                                \
            cp16(ab_ + so_, asrc_);                                          \
            cp16(bb_ + so_, gB + (size_t)r_ * KC + k0_ + c_ * 8);            \
        }                                                                    \
    } while (0)

    const int NS = KC / 64;

    LOAD_SLAB(0, 0); CP_COMMIT();
    LOAD_SLAB(1, 1); CP_COMMIT();

    if (tid < 128) {
        if (PERM == 1) {
            size_t r = perm_fwd(m0 + tid);
            int win = (int)(r / 49), t = (int)(r - (size_t)win * 49);
            int mat   = n0 >> 8;
            int head0 = (n0 & 255) >> 5;
            rowbase[tid] = ((win * 3 + mat) * 8 + head0) * 1568 + t * 32;
        } else {
            rowbase[tid] = (int)(perm_inv(m0 + tid) * 256);
        }
    }

    const int aRow = wm * 32 + (lane & 15);
    const int aChk = lane >> 4;
    const int bRowBase = wn * 64 + (lane & 7) + ((lane >> 4) << 3);
    const int bChk = (lane >> 3) & 1;

    for (int f = 0; f < NS; f++) {
        CP_WAIT1();
        __syncthreads();

        const int st = (f < 3) ? f : 0;
        const uint32_t aBase = s0 + st * ST;
        const uint32_t bBase = aBase + MAT_ST;
#pragma unroll
        for (int kk = 0; kk < 4; kk++) {
            uint32_t af[2][4];
#pragma unroll
            for (int mt = 0; mt < 2; mt++) {
                uint32_t ad = aBase + (aRow + mt * 16) * MROW +
                              (kk * 2 + aChk) * 16;
                ldsm4(af[mt][0], af[mt][1], af[mt][2], af[mt][3], ad);
            }
            uint32_t bf[8][2];
#pragma unroll
            for (int pr = 0; pr < 4; pr++) {
                uint32_t bd = bBase + (bRowBase + pr * 16) * MROW +
                              (kk * 2 + bChk) * 16;
                uint32_t r0, r1, r2, r3;
                ldsm4(r0, r1, r2, r3, bd);
                bf[2 * pr][0] = r0; bf[2 * pr][1] = r1;
                bf[2 * pr + 1][0] = r2; bf[2 * pr + 1][1] = r3;
            }
#pragma unroll
            for (int mt = 0; mt < 2; mt++)
#pragma unroll
                for (int nt = 0; nt < 8; nt++)
                    mma16816(acc[mt][nt], af[mt], bf[nt]);
        }

        if (f + 2 < NS) {
            int st2 = f + 2 - 3 < 0 ? f + 2 : f - 1;
            LOAD_SLAB(st2, f + 2);
        }
        CP_COMMIT();
    }
#undef LOAD_SLAB

    CP_WAIT0();
    __syncthreads();

    const int g  = lane >> 2;
    const int t4 = lane & 3;

    if constexpr (PERM == 1) {
        __half* S = smbuf;
#pragma unroll
        for (int nt = 0; nt < 8; nt++) {
            const int col = wn * 64 + nt * 8 + 2 * t4;
            float2 bb = *(const float2*)(bias + n0 + col);
#pragma unroll
            for (int mt = 0; mt < 2; mt++) {
                int row = wm * 32 + mt * 16 + g;
                *(__half2*)(S + row * 136 + col) =
                    __floats2half2_rn(acc[mt][nt][0] + bb.x,
                                      acc[mt][nt][1] + bb.y);
                *(__half2*)(S + (row + 8) * 136 + col) =
                    __floats2half2_rn(acc[mt][nt][2] + bb.x,
                                      acc[mt][nt][3] + bb.y);
            }
        }
        __syncthreads();
        __half* Cb = (__half*)C;
#pragma unroll
        for (int i = 0; i < 8; i++) {
            int idx = tid + i * 256;
            int r = idx >> 4, c = (idx >> 2) & 3, q = idx & 3;
            uint4 v = *(const uint4*)(S + r * 136 + c * 32 + q * 8);
            *(uint4*)(Cb + (size_t)rowbase[r] + c * 1568 + q * 8) = v;
        }
    } else {
        float* S = (float*)smbuf;
#pragma unroll
        for (int nt = 0; nt < 8; nt++) {
            const int col = wn * 64 + nt * 8 + 2 * t4;
            float2 bb = *(const float2*)(bias + n0 + col);
#pragma unroll
            for (int mt = 0; mt < 2; mt++) {
                int row = wm * 32 + mt * 16 + g;
                *(float2*)(S + row * 132 + col) =
                    make_float2(acc[mt][nt][0] + bb.x, acc[mt][nt][1] + bb.y);
                *(float2*)(S + (row + 8) * 132 + col) =
                    make_float2(acc[mt][nt][2] + bb.x, acc[mt][nt][3] + bb.y);
            }
        }
        __syncthreads();
        float* Cf = (float*)C;
#pragma unroll
        for (int i = 0; i < 16; i++) {
            int idx = tid + i * 256;
            int r = idx >> 5, q = idx & 31;
            uint4 v = *(const uint4*)(S + r * 132 + q * 4);
            *(uint4*)(Cf + (size_t)rowbase[r] + n0 + q * 4) = v;
        }
    }
}

// ======================= tensor-core attention ==============================
// Block = (chunk of 8 windows, type, head). 128 threads, 4 warps, one m16
// row tile per warp. Table staged once; QKV double-buffered via cp.async.
__global__ void __launch_bounds__(128)
attn_mma(const __half* __restrict__ qkv, const __half* __restrict__ tblg,
         __half* __restrict__ outp) {
    __shared__ __align__(16) __half Qs[2][64 * 40];
    __shared__ __align__(16) __half Ks[2][64 * 40];
    __shared__ __align__(16) __half Vs[2][64 * 40];
    __shared__ __align__(16) __half Ts[64 * 72];

    const int tid   = threadIdx.x;
    const int w     = tid >> 5;
    const int lane  = tid & 31;
    const int combo = blockIdx.y;        // type*8 + head
    const int head  = combo & 7;
    const int type  = combo >> 3;
    const int chunk = blockIdx.x;

    const int chunks4[4] = {196, 28, 28, 4};
    if (chunk >= chunks4[type]) return;

    // window id for k-th window in this chunk
    int wins[8];
#pragma unroll
    for (int k = 0; k < 8; k++) {
        int i = chunk * 8 + k;
        int b, wr, wc;
        if (type == 0)      { b = i / 49; int r = i % 49; wr = r / 7; wc = r % 7; }
        else if (type == 1) { b = i / 7;  wr = i % 7; wc = 7; }
        else if (type == 2) { b = i / 7;  wr = 7; wc = i % 7; }
        else                { b = i;      wr = 7; wc = 7; }
        wins[k] = b * 64 + wr * 8 + wc;
    }

    // stage table once
    {
        const uint4* Tg = (const uint4*)(tblg + (size_t)combo * 4096);
        for (int idx = tid; idx < 512; idx += 128) {
            int r = idx >> 3, c = idx & 7;
            *(uint4*)(Ts + r * 72 + c * 8) = Tg[idx];
        }
    }
    // zero pad rows 49..63 in BOTH buffers (15 rows x 4 chunks x 3 mats x 2)
    for (int idx = tid; idx < 360; idx += 128) {
        int buf = idx / 180, rem = idx - buf * 180;
        int mat = rem / 60, rem2 = rem - mat * 60;
        int r = 49 + (rem2 >> 2), q = rem2 & 3;
        __half* bp = (mat == 0) ? Qs[buf] : (mat == 1) ? Ks[buf] : Vs[buf];
        *(uint4*)(bp + r * 40 + q * 8) = make_uint4(0, 0, 0, 0);
    }

#define PREFETCH(k, buf)                                                     \
    do {                                                                     \
        const __half* srcQ_ = qkv + ((size_t)wins[k] * 24 + head) * 1568;    \
        for (int idx = tid; idx < 588; idx += 128) {                         \
            int mat_ = idx / 196, r_ = idx - mat_ * 196;                     \
            int p_ = r_ >> 2, q_ = r_ & 3;                                   \
            const __half* src_ = srcQ_ + mat_ * (8 * 1568) + p_ * 32 + q_ * 8;\
            __half* d_ = (mat_ == 0) ? Qs[buf] : (mat_ == 1) ? Ks[buf]       \
                                                             : Vs[buf];     \
            cp16(smem_u32(d_ + p_ * 40 + q_ * 8), src_);                     \
        }                                                                    \
    } while (0)

    PREFETCH(0, 0);
    CP_COMMIT();

    const int g  = lane >> 2;
    const int t4 = lane & 3;
    const float scale = 0.17677669529663687f;

    for (int k = 0; k < 8; k++) {
        const int buf = k & 1;
        if (k + 1 < 8) PREFETCH(k + 1, buf ^ 1);
        CP_COMMIT();
        CP_WAIT1();
        __syncthreads();

        const uint32_t sQ = smem_u32(Qs[buf]);
        const uint32_t sK = smem_u32(Ks[buf]);
        const uint32_t sV = smem_u32(Vs[buf]);

        // ---- S = Q K^T ----
        uint32_t aQ[2][4];
#pragma unroll
        for (int kk = 0; kk < 2; kk++) {
            int row = w * 16 + (lane & 15);
            uint32_t ad = sQ + row * 80 + (kk * 2 + (lane >> 4)) * 16;
            ldsm4(aQ[kk][0], aQ[kk][1], aQ[kk][2], aQ[kk][3], ad);
        }
        uint32_t bK[2][8][2];
#pragma unroll
        for (int kk = 0; kk < 2; kk++)
#pragma unroll
            for (int pr = 0; pr < 4; pr++) {
                int row = pr * 16 + (lane & 7) + ((lane >> 4) << 3);
                uint32_t ad = sK + row * 80 + (kk * 2 + ((lane >> 3) & 1)) * 16;
                uint32_t r0, r1, r2, r3;
                ldsm4(r0, r1, r2, r3, ad);
                bK[kk][2 * pr][0] = r0;     bK[kk][2 * pr][1] = r1;
                bK[kk][2 * pr + 1][0] = r2; bK[kk][2 * pr + 1][1] = r3;
            }
        float s[8][4];
#pragma unroll
        for (int nt = 0; nt < 8; nt++) {
            s[nt][0] = s[nt][1] = s[nt][2] = s[nt][3] = 0.f;
            mma16816(s[nt], aQ[0], bK[0][nt]);
            mma16816(s[nt], aQ[1], bK[1][nt]);
        }

        // ---- logits ----
#pragma unroll
        for (int h = 0; h < 2; h++) {
            const __half* trow = Ts + (w * 16 + g + 8 * h) * 72;
#pragma unroll
            for (int nt = 0; nt < 8; nt++) {
                __half2 t2 = *(const __half2*)(trow + nt * 8 + 2 * t4);
                float2 tf = __half22float2(t2);
                s[nt][2 * h]     = fmaf(s[nt][2 * h],     scale, tf.x);
                s[nt][2 * h + 1] = fmaf(s[nt][2 * h + 1], scale, tf.y);
            }
        }

        // ---- softmax ----
        float zinv[2];
#pragma unroll
        for (int h = 0; h < 2; h++) {
            float m = -1e30f;
#pragma unroll
            for (int nt = 0; nt < 8; nt++) {
                m = fmaxf(m, s[nt][2 * h]);
                m = fmaxf(m, s[nt][2 * h + 1]);
            }
            m = fmaxf(m, __shfl_xor_sync(0xffffffffu, m, 1));
            m = fmaxf(m, __shfl_xor_sync(0xffffffffu, m, 2));
            float sum = 0.f;
#pragma unroll
            for (int nt = 0; nt < 8; nt++) {
                float e0 = __expf(s[nt][2 * h] - m);
                float e1 = __expf(s[nt][2 * h + 1] - m);
                s[nt][2 * h] = e0;
                s[nt][2 * h + 1] = e1;
                sum += e0 + e1;
            }
            sum += __shfl_xor_sync(0xffffffffu, sum, 1);
            sum += __shfl_xor_sync(0xffffffffu, sum, 2);
            zinv[h] = 1.0f / sum;
        }

        // ---- P fragments ----
        uint32_t aP[4][4];
#pragma unroll
        for (int kt = 0; kt < 4; kt++) {
            aP[kt][0] = h2u(__floats2half2_rn(s[2 * kt][0], s[2 * kt][1]));
            aP[kt][1] = h2u(__floats2half2_rn(s[2 * kt][2], s[2 * kt][3]));
            aP[kt][2] = h2u(__floats2half2_rn(s[2 * kt + 1][0], s[2 * kt + 1][1]));
            aP[kt][3] = h2u(__floats2half2_rn(s[2 * kt + 1][2], s[2 * kt + 1][3]));
        }

        // ---- V fragments ----
        uint32_t bV[4][4][2];
#pragma unroll
        for (int kt = 0; kt < 4; kt++)
#pragma unroll
            for (int nh = 0; nh < 2; nh++) {
                int row = kt * 16 + (lane & 7) + (((lane >> 3) & 1) << 3);
                uint32_t ad = sV + row * 80 + nh * 32 + ((lane >> 4) << 4);
                uint32_t r0, r1, r2, r3;
                ldsm4t(r0, r1, r2, r3, ad);
                bV[kt][2 * nh][0] = r0;     bV[kt][2 * nh][1] = r1;
                bV[kt][2 * nh + 1][0] = r2; bV[kt][2 * nh + 1][1] = r3;
            }

        // ---- O = P V ----
        float o[4][4];
#pragma unroll
        for (int vn = 0; vn < 4; vn++) {
            o[vn][0] = o[vn][1] = o[vn][2] = o[vn][3] = 0.f;
#pragma unroll
            for (int kt = 0; kt < 4; kt++)
                mma16816(o[vn], aP[kt], bV[kt][vn]);
        }

        // ---- store ----
        __half* obase = outp + ((size_t)wins[k] * 8 + head) * 1568;
#pragma unroll
        for (int h = 0; h < 2; h++) {
            int i = w * 16 + g + 8 * h;
            if (i < 49) {
                float rz = zinv[h];
                __half* dst = obase + i * 32;
#pragma unroll
                for (int vn = 0; vn < 4; vn++) {
                    int col = vn * 8 + 2 * t4;
                    *(__half2*)(dst + col) =
                        __floats2half2_rn(o[vn][2 * h] * rz,
                                          o[vn][2 * h + 1] * rz);
                }
            }
        }
        __syncthreads();   // done reading buf before it is overwritten
    }
#undef PREFETCH
}

// ---------------------------------------------------------------------------
extern "C" void kernel_launch(void* const* d_in, const int* in_sizes, int n_in,
                              void* d_out, int out_size) {
    const float* x      = (const float*)d_in[0];
    const float* qkv_w  = (const float*)d_in[1];
    const float* qkv_b  = (const float*)d_in[2];
    const float* proj_w = (const float*)d_in[3];
    const float* proj_b = (const float*)d_in[4];
    const float* table  = (const float*)d_in[5];
    float* out = (float*)d_out;

    void *qkv_p, *x16_p, *acat_p, *wq_p, *wp_p, *tbl_p;
    cudaGetSymbolAddress(&qkv_p,  g_qkv);
    cudaGetSymbolAddress(&x16_p,  g_x16);
    cudaGetSymbolAddress(&acat_p, g_acat);
    cudaGetSymbolAddress(&wq_p,   g_wq);
    cudaGetSymbolAddress(&wp_p,   g_wp);
    cudaGetSymbolAddress(&tbl_p,  g_tbl);
    __half* qkv  = (__half*)qkv_p;
    __half* x16  = (__half*)x16_p;
    __half* acat = (__half*)acat_p;
    __half* wq   = (__half*)wq_p;
    __half* wp   = (__half*)wp_p;
    __half* tbl  = (__half*)tbl_p;

    static bool attr_done = false;
    if (!attr_done) {
        cudaFuncSetAttribute((const void*)gemm_mma<__half, 1>,
                             cudaFuncAttributeMaxDynamicSharedMemorySize,
                             GEMM_SMEM);
        cudaFuncSetAttribute((const void*)gemm_mma<float, 2>,
                             cudaFuncAttributeMaxDynamicSharedMemorySize,
                             GEMM_SMEM);
        attr_done = true;
    }

    convert_h<<<(M_ROWS * 64 + 255) / 256, 256>>>(x, x16, M_ROWS * 64);
    convert_h<<<(768 * 64 + 255) / 256, 256>>>(qkv_w, wq, 768 * 64);
    convert_h<<<(256 * 64 + 255) / 256, 256>>>(proj_w, wp, 256 * 64);
    build_tbl<<<32, 256>>>(table, tbl);

    dim3 gq(768 / 128, M_ROWS / 128);
    gemm_mma<__half, 1><<<gq, 256, GEMM_SMEM>>>(x16, wq, qkv_b, qkv, 768);

    dim3 ga(196, 32);
    attn_mma<<<ga, 128>>>(qkv, tbl, acat);

    dim3 gp(256 / 128, M_ROWS / 128);
    gemm_mma<float, 2><<<gp, 256, GEMM_SMEM>>>(acat, wp, proj_b, out, 256);
}